// round 5
// baseline (speedup 1.0000x reference)
#include <cuda_runtime.h>
#include <cstdint>

#define T_LEN 32768
#define DM 512
#define DH 512
#define LCH 32
#define NCH (T_LEN / LCH)   // 1024 chunks

// ---------------- device scratch (no runtime allocations allowed) ----------------
__device__ float g_Bu_re[(size_t)T_LEN * DH];   // 64 MB
__device__ float g_Bu_im[(size_t)T_LEN * DH];   // 64 MB
__device__ float g_xs_re[(size_t)T_LEN * DH];   // 64 MB
__device__ float g_xs_im[(size_t)T_LEN * DH];   // 64 MB
__device__ float g_lam_re[DH], g_lam_im[DH], g_gam[DH];
__device__ float g_lamL_re[DH], g_lamL_im[DH];
__device__ float g_cb_re[NCH * DH], g_cb_im[NCH * DH];
__device__ float g_init_re[NCH * DH], g_init_im[NCH * DH];
__device__ int   g_anystart[NCH];
__device__ unsigned char g_start[T_LEN];

// ---------------- start-flag dtype detection + normalization ----------------
// Empirically (identical rel_err across rounds with both paths live) start is
// 0/1 int32 words; keep the detection anyway — it is cheap and robust.
__global__ void start_convert_kernel(const unsigned int* __restrict__ raw) {
    __shared__ int s_isu8;
    int tid = threadIdx.x;
    if (tid == 0) s_isu8 = 0;
    __syncthreads();
    for (int i = tid; i < T_LEN / 4; i += blockDim.x)
        if (raw[i] > 1u) s_isu8 = 1;      // racy benign write
    __syncthreads();
    if (s_isu8) {
        const unsigned char* b = (const unsigned char*)raw;
        for (int t = tid; t < T_LEN; t += blockDim.x)
            g_start[t] = b[t] ? 1 : 0;
    } else {
        for (int t = tid; t < T_LEN; t += blockDim.x)
            g_start[t] = raw[t] ? 1 : 0;
    }
}

// ---------------- prep: lambda, gamma, lambda^L ----------------
__global__ void prep_kernel(const float* __restrict__ theta_log,
                            const float* __restrict__ nu_log,
                            const float* __restrict__ gamma_log) {
    int h = threadIdx.x;
    float nu = expf(nu_log[h]);
    float th = expf(theta_log[h]);
    float mag = expf(-nu);
    float lr = mag * cosf(th);
    float li = mag * sinf(th);
    g_lam_re[h] = lr;
    g_lam_im[h] = li;
    g_gam[h] = expf(gamma_log[h]);
    float ar = 1.f, ai = 0.f;
#pragma unroll
    for (int i = 0; i < LCH; i++) {
        float nr = ar * lr - ai * li;
        float ni = ar * li + ai * lr;
        ar = nr; ai = ni;
    }
    g_lamL_re[h] = ar;
    g_lamL_im[h] = ai;
}

// ---------------- GEMM1: Bu[t,h] = gam[h] * sum_m x[t,m]*B[h,m] ----------------
__global__ __launch_bounds__(256) void gemm_bu_kernel(
    const float* __restrict__ A,   // x:  (T, 512) row-major
    const float* __restrict__ B,   // B_re or B_im: (512, 512) row-major [h, m]
    int plane)
{
    float* Cout = plane ? g_Bu_im : g_Bu_re;
    __shared__ float As[8][128];
    __shared__ float Bs[8][128];
    int tid = threadIdx.x;
    int n0 = blockIdx.x * 128;   // h tile
    int m0 = blockIdx.y * 128;   // t tile
    int lr = tid >> 1;
    int lc = (tid & 1) * 4;
    const float* Ag = A + (size_t)(m0 + lr) * DM + lc;
    const float* Bg = B + (size_t)(n0 + lr) * DM + lc;
    int ty = tid >> 4;
    int tx = tid & 15;

    float acc[8][8];
#pragma unroll
    for (int i = 0; i < 8; i++)
#pragma unroll
        for (int j = 0; j < 8; j++) acc[i][j] = 0.f;

    for (int k0 = 0; k0 < DM; k0 += 8) {
        float4 av = *(const float4*)(Ag + k0);
        float4 bv = *(const float4*)(Bg + k0);
        __syncthreads();
        As[lc + 0][lr] = av.x; As[lc + 1][lr] = av.y;
        As[lc + 2][lr] = av.z; As[lc + 3][lr] = av.w;
        Bs[lc + 0][lr] = bv.x; Bs[lc + 1][lr] = bv.y;
        Bs[lc + 2][lr] = bv.z; Bs[lc + 3][lr] = bv.w;
        __syncthreads();
#pragma unroll
        for (int k = 0; k < 8; k++) {
            float4 a0 = *(const float4*)&As[k][ty * 8];
            float4 a1 = *(const float4*)&As[k][ty * 8 + 4];
            float4 b0 = *(const float4*)&Bs[k][tx * 8];
            float4 b1 = *(const float4*)&Bs[k][tx * 8 + 4];
            float a[8] = {a0.x, a0.y, a0.z, a0.w, a1.x, a1.y, a1.z, a1.w};
            float b[8] = {b0.x, b0.y, b0.z, b0.w, b1.x, b1.y, b1.z, b1.w};
#pragma unroll
            for (int i = 0; i < 8; i++)
#pragma unroll
                for (int j = 0; j < 8; j++) acc[i][j] += a[i] * b[j];
        }
    }
#pragma unroll
    for (int i = 0; i < 8; i++) {
        int row = m0 + ty * 8 + i;
#pragma unroll
        for (int j = 0; j < 8; j++) {
            int col = n0 + tx * 8 + j;
            Cout[(size_t)row * DH + col] = acc[i][j] * g_gam[col];
        }
    }
}

// ---------------- scan pass A: per-chunk reduce ----------------
__global__ void chunk_reduce_kernel() {
    int c = blockIdx.x;
    int h = threadIdx.x;
    float lr = g_lam_re[h], li = g_lam_im[h];
    float sr = 0.f, si = 0.f;
    int any = 0;
    int base = c * LCH;
#pragma unroll 4
    for (int t = 0; t < LCH; t++) {
        int s = g_start[base + t];
        any |= s;
        float br = g_Bu_re[(size_t)(base + t) * DH + h];
        float bi = g_Bu_im[(size_t)(base + t) * DH + h];
        if (s) { sr = br; si = bi; }
        else {
            float nr = lr * sr - li * si + br;
            float ni = lr * si + li * sr + bi;
            sr = nr; si = ni;
        }
    }
    g_cb_re[c * DH + h] = sr;
    g_cb_im[c * DH + h] = si;
    if (h == 0) g_anystart[c] = any;
}

// ---------------- scan pass B: sequential scan over chunk carries ----------------
__global__ void chunk_scan_kernel(const float* __restrict__ state) {
    int h = threadIdx.x;
    float sr = state[h], si = 0.f;
    float Lr = g_lamL_re[h], Li = g_lamL_im[h];
    for (int c = 0; c < NCH; c++) {
        g_init_re[c * DH + h] = sr;
        g_init_im[c * DH + h] = si;
        float br = g_cb_re[c * DH + h];
        float bi = g_cb_im[c * DH + h];
        if (g_anystart[c]) { sr = br; si = bi; }
        else {
            float nr = Lr * sr - Li * si + br;
            float ni = Lr * si + Li * sr + bi;
            sr = nr; si = ni;
        }
    }
}

// ---------------- scan pass C: expand with correct chunk-initial states ----------------
__global__ void chunk_expand_kernel() {
    int c = blockIdx.x;
    int h = threadIdx.x;
    float lr = g_lam_re[h], li = g_lam_im[h];
    float sr = g_init_re[c * DH + h];
    float si = g_init_im[c * DH + h];
    int base = c * LCH;
#pragma unroll 4
    for (int t = 0; t < LCH; t++) {
        float br = g_Bu_re[(size_t)(base + t) * DH + h];
        float bi = g_Bu_im[(size_t)(base + t) * DH + h];
        if (g_start[base + t]) { sr = br; si = bi; }
        else {
            float nr = lr * sr - li * si + br;
            float ni = lr * si + li * sr + bi;
            sr = nr; si = ni;
        }
        g_xs_re[(size_t)(base + t) * DH + h] = sr;
        g_xs_im[(size_t)(base + t) * DH + h] = si;
    }
}

// ---------------- GEMM2: out[t,m] = sum_h xs_re*C_re - xs_im*C_im + x*D ----------------
__global__ __launch_bounds__(256) void gemm_out_kernel(
    const float* __restrict__ Cre,  // (512, 512) [m, h]
    const float* __restrict__ Cim,
    const float* __restrict__ x,
    const float* __restrict__ Dvec,
    float* __restrict__ out)        // already offset to outputs region
{
    __shared__ float As[8][128];
    __shared__ float Bs[8][128];
    int tid = threadIdx.x;
    int n0 = blockIdx.x * 128;   // m tile
    int m0 = blockIdx.y * 128;   // t tile
    int lr = tid >> 1;
    int lc = (tid & 1) * 4;
    int ty = tid >> 4;
    int tx = tid & 15;

    float acc[8][8];
#pragma unroll
    for (int i = 0; i < 8; i++)
#pragma unroll
        for (int j = 0; j < 8; j++) acc[i][j] = 0.f;

    for (int k0 = 0; k0 < 2 * DH; k0 += 8) {
        const float* Ab;
        const float* Bb;
        float sgn;
        int kk;
        if (k0 < DH) { Ab = g_xs_re; Bb = Cre; sgn = 1.f; kk = k0; }
        else         { Ab = g_xs_im; Bb = Cim; sgn = -1.f; kk = k0 - DH; }
        float4 av = *(const float4*)(Ab + (size_t)(m0 + lr) * DH + kk + lc);
        float4 bv = *(const float4*)(Bb + (size_t)(n0 + lr) * DH + kk + lc);
        __syncthreads();
        As[lc + 0][lr] = av.x * sgn; As[lc + 1][lr] = av.y * sgn;
        As[lc + 2][lr] = av.z * sgn; As[lc + 3][lr] = av.w * sgn;
        Bs[lc + 0][lr] = bv.x; Bs[lc + 1][lr] = bv.y;
        Bs[lc + 2][lr] = bv.z; Bs[lc + 3][lr] = bv.w;
        __syncthreads();
#pragma unroll
        for (int k = 0; k < 8; k++) {
            float4 a0 = *(const float4*)&As[k][ty * 8];
            float4 a1 = *(const float4*)&As[k][ty * 8 + 4];
            float4 b0 = *(const float4*)&Bs[k][tx * 8];
            float4 b1 = *(const float4*)&Bs[k][tx * 8 + 4];
            float a[8] = {a0.x, a0.y, a0.z, a0.w, a1.x, a1.y, a1.z, a1.w};
            float b[8] = {b0.x, b0.y, b0.z, b0.w, b1.x, b1.y, b1.z, b1.w};
#pragma unroll
            for (int i = 0; i < 8; i++)
#pragma unroll
                for (int j = 0; j < 8; j++) acc[i][j] += a[i] * b[j];
        }
    }
#pragma unroll
    for (int i = 0; i < 8; i++) {
        int row = m0 + ty * 8 + i;
#pragma unroll
        for (int j = 0; j < 8; j++) {
            int col = n0 + tx * 8 + j;
            out[(size_t)row * DM + col] =
                acc[i][j] + x[(size_t)row * DM + col] * Dvec[col];
        }
    }
}

// ---------------- final state writer ----------------
// mode 0: two floats per element, PLANAR  [re x 512][im x 512]
// mode 1: real part only                  [re x 512]
// mode 2: two floats per element, interleaved (complex64 bytes)
__global__ void write_state_kernel(float* __restrict__ out, int mode) {
    int h = threadIdx.x;
    float re = g_xs_re[(size_t)(T_LEN - 1) * DH + h];
    float im = g_xs_im[(size_t)(T_LEN - 1) * DH + h];
    if (mode == 0) { out[h] = re; out[DH + h] = im; }
    else if (mode == 1) { out[h] = re; }
    else { out[2 * h] = re; out[2 * h + 1] = im; }
}

// ---------------- launch ----------------
extern "C" void kernel_launch(void* const* d_in, const int* in_sizes, int n_in,
                              void* d_out, int out_size) {
    // metadata order: state, x, start, theta_log, nu_log, gamma_log,
    //                 B_re, B_im, C_re, C_im, D
    const float*        state     = (const float*)d_in[0];
    const float*        x         = (const float*)d_in[1];
    const unsigned int* start_raw = (const unsigned int*)d_in[2];
    const float*        theta_log = (const float*)d_in[3];
    const float*        nu_log    = (const float*)d_in[4];
    const float*        gamma_log = (const float*)d_in[5];
    const float*        B_re      = (const float*)d_in[6];
    const float*        B_im      = (const float*)d_in[7];
    const float*        C_re      = (const float*)d_in[8];
    const float*        C_im      = (const float*)d_in[9];
    const float*        Dvec      = (const float*)d_in[10];

    // Resolve the d_out layout from out_size.
    //   T*DM + 2*DH  -> complex state kept as 2 floats (try PLANAR; interleaved failed)
    //   T*DM +   DH  -> state converted to real-only, outputs at offset DH
    const long long full = (long long)T_LEN * DM;
    int state_elems = (int)((long long)out_size - full);   // 1024 or 512
    int mode;                                              // see write_state_kernel
    int out_off;
    if (state_elems >= 2 * DH) { mode = 0; out_off = 2 * DH; }
    else                       { mode = 1; out_off = DH; }

    float* out = (float*)d_out;
    float* outputs = out + out_off;

    start_convert_kernel<<<1, 256>>>(start_raw);
    prep_kernel<<<1, DH>>>(theta_log, nu_log, gamma_log);

    dim3 ggrid(DH / 128, T_LEN / 128);
    gemm_bu_kernel<<<ggrid, 256>>>(x, B_re, 0);
    gemm_bu_kernel<<<ggrid, 256>>>(x, B_im, 1);

    chunk_reduce_kernel<<<NCH, DH>>>();
    chunk_scan_kernel<<<1, DH>>>(state);
    chunk_expand_kernel<<<NCH, DH>>>();

    dim3 ogrid(DM / 128, T_LEN / 128);
    gemm_out_kernel<<<ogrid, 256>>>(C_re, C_im, x, Dvec, outputs);

    write_state_kernel<<<1, DH>>>(out, mode);
}

// round 6
// speedup vs baseline: 2.0858x; 2.0858x over previous
#include <cuda_runtime.h>
#include <cstdint>

#define T_LEN 32768
#define DM 512
#define DH 512
#define LCH 32
#define NCH (T_LEN / LCH)   // 1024 chunks

// ---------------- device scratch (no runtime allocations allowed) ----------------
__device__ float g_Bu_re[(size_t)T_LEN * DH];   // 64 MB
__device__ float g_Bu_im[(size_t)T_LEN * DH];   // 64 MB
__device__ float g_xs_re[(size_t)T_LEN * DH];   // 64 MB
__device__ float g_xs_im[(size_t)T_LEN * DH];   // 64 MB
__device__ float g_lam_re[DH], g_lam_im[DH], g_gam[DH];
__device__ float g_lamL_re[DH], g_lamL_im[DH];
__device__ float g_cb_re[NCH * DH], g_cb_im[NCH * DH];
__device__ float g_init_re[NCH * DH], g_init_im[NCH * DH];
__device__ int   g_anystart[NCH];
__device__ unsigned char g_start[T_LEN];

// ---------------- start-flag dtype detection + normalization ----------------
__global__ void start_convert_kernel(const unsigned int* __restrict__ raw) {
    __shared__ int s_isu8;
    int tid = threadIdx.x;
    if (tid == 0) s_isu8 = 0;
    __syncthreads();
    for (int i = tid; i < T_LEN / 4; i += blockDim.x)
        if (raw[i] > 1u) s_isu8 = 1;      // racy benign write
    __syncthreads();
    if (s_isu8) {
        const unsigned char* b = (const unsigned char*)raw;
        for (int t = tid; t < T_LEN; t += blockDim.x)
            g_start[t] = b[t] ? 1 : 0;
    } else {
        for (int t = tid; t < T_LEN; t += blockDim.x)
            g_start[t] = raw[t] ? 1 : 0;
    }
}

// ---------------- prep: lambda, gamma, lambda^L ----------------
__global__ void prep_kernel(const float* __restrict__ theta_log,
                            const float* __restrict__ nu_log,
                            const float* __restrict__ gamma_log) {
    int h = threadIdx.x;
    float nu = expf(nu_log[h]);
    float th = expf(theta_log[h]);
    float mag = expf(-nu);
    float lr = mag * cosf(th);
    float li = mag * sinf(th);
    g_lam_re[h] = lr;
    g_lam_im[h] = li;
    g_gam[h] = expf(gamma_log[h]);
    float ar = 1.f, ai = 0.f;
#pragma unroll
    for (int i = 0; i < LCH; i++) {
        float nr = ar * lr - ai * li;
        float ni = ar * li + ai * lr;
        ar = nr; ai = ni;
    }
    g_lamL_re[h] = ar;
    g_lamL_im[h] = ai;
}

// ---------------- tf32 helpers ----------------
__device__ __forceinline__ unsigned f2tf32(float x) {
    unsigned u;
    asm("cvt.rna.tf32.f32 %0, %1;" : "=r"(u) : "f"(x));
    return u;
}

__device__ __forceinline__ void mma_tf32(float& c0, float& c1, float& c2, float& c3,
                                         unsigned a0, unsigned a1, unsigned a2, unsigned a3,
                                         unsigned b0, unsigned b1) {
    asm volatile(
        "mma.sync.aligned.m16n8k8.row.col.f32.tf32.tf32.f32 "
        "{%0,%1,%2,%3}, {%4,%5,%6,%7}, {%8,%9}, {%0,%1,%2,%3};"
        : "+f"(c0), "+f"(c1), "+f"(c2), "+f"(c3)
        : "r"(a0), "r"(a1), "r"(a2), "r"(a3), "r"(b0), "r"(b1));
}

// ---------------- tensor-core GEMM (tf32) ----------------
// mode 0: Bu planes.  A = x (T,512);  B = (blockIdx.z ? B_im : B_re) (512,512) [h,m].
//         Cout = (blockIdx.z ? g_Bu_im : g_Bu_re),  epilogue: * gam[col]. K=512.
// mode 2: outputs.    A = g_xs_re then g_xs_im;  B = C_re then -C_im. K=1024.
//         Cout = external outputs,  epilogue: + x*D.
// Tile: 128x128, BK=16 double-buffered, 8 warps (2m x 4n), warp tile 64x32.
#define BK 16
#define SMS 132   // padded row stride (floats): bank = (4k+m)%32, conflict-free frags

__global__ __launch_bounds__(256) void gemm_tc_kernel(
    const float* __restrict__ Agl,
    const float* __restrict__ B0,
    const float* __restrict__ B1,
    const float* __restrict__ x,
    const float* __restrict__ Dvec,
    float* __restrict__ Cout_ext,
    int mode)
{
    __shared__ unsigned As[2][BK][SMS];
    __shared__ unsigned Bs[2][BK][SMS];

    const int t    = threadIdx.x;
    const int lane = t & 31;
    const int wid  = t >> 5;
    const int wm0  = (wid >> 2) * 64;   // warp m offset in tile
    const int wn0  = (wid & 3) * 32;    // warp n offset in tile
    const int m0   = blockIdx.y * 128;
    const int n0   = blockIdx.x * 128;

    float* Cout;
    int KT;
    if (mode == 0) {
        Cout = blockIdx.z ? g_Bu_im : g_Bu_re;
        KT = DM / BK;               // 32
    } else {
        Cout = Cout_ext;
        KT = 2 * DH / BK;           // 64
    }

    const int lrow = t >> 2;        // 0..63, gmem load row within half-tile
    const int lk   = (t & 3) * 4;   // k quad

    float acc[4][4][4];
#pragma unroll
    for (int a = 0; a < 4; a++)
#pragma unroll
        for (int b = 0; b < 4; b++)
#pragma unroll
            for (int c = 0; c < 4; c++) acc[a][b][c] = 0.f;

    // ---- tile source resolution ----
    const float* Ap; const float* Bp; float sgn; int kb;
#define SET_SRC(kt) do {                                              \
        int kg = (kt) * BK;                                           \
        if (mode == 0) { Ap = Agl; Bp = blockIdx.z ? B1 : B0; sgn = 1.f; kb = kg; } \
        else if (kg < DH) { Ap = g_xs_re; Bp = B0; sgn = 1.f;  kb = kg; }           \
        else              { Ap = g_xs_im; Bp = B1; sgn = -1.f; kb = kg - DH; }      \
    } while (0)

    float4 ra0, ra1, rb0, rb1;
#define FETCH() do {                                                                  \
        ra0 = *(const float4*)&Ap[(size_t)(m0 + lrow) * DM + kb + lk];                \
        ra1 = *(const float4*)&Ap[(size_t)(m0 + lrow + 64) * DM + kb + lk];           \
        rb0 = *(const float4*)&Bp[(size_t)(n0 + lrow) * DM + kb + lk];                \
        rb1 = *(const float4*)&Bp[(size_t)(n0 + lrow + 64) * DM + kb + lk];           \
    } while (0)

#define STORE(buf) do {                                                \
        As[buf][lk + 0][lrow] = f2tf32(ra0.x);                         \
        As[buf][lk + 1][lrow] = f2tf32(ra0.y);                         \
        As[buf][lk + 2][lrow] = f2tf32(ra0.z);                         \
        As[buf][lk + 3][lrow] = f2tf32(ra0.w);                         \
        As[buf][lk + 0][lrow + 64] = f2tf32(ra1.x);                    \
        As[buf][lk + 1][lrow + 64] = f2tf32(ra1.y);                    \
        As[buf][lk + 2][lrow + 64] = f2tf32(ra1.z);                    \
        As[buf][lk + 3][lrow + 64] = f2tf32(ra1.w);                    \
        Bs[buf][lk + 0][lrow] = f2tf32(rb0.x * sgn);                   \
        Bs[buf][lk + 1][lrow] = f2tf32(rb0.y * sgn);                   \
        Bs[buf][lk + 2][lrow] = f2tf32(rb0.z * sgn);                   \
        Bs[buf][lk + 3][lrow] = f2tf32(rb0.w * sgn);                   \
        Bs[buf][lk + 0][lrow + 64] = f2tf32(rb1.x * sgn);              \
        Bs[buf][lk + 1][lrow + 64] = f2tf32(rb1.y * sgn);              \
        Bs[buf][lk + 2][lrow + 64] = f2tf32(rb1.z * sgn);              \
        Bs[buf][lk + 3][lrow + 64] = f2tf32(rb1.w * sgn);              \
    } while (0)

    SET_SRC(0); FETCH(); STORE(0);
    __syncthreads();

    for (int kt = 0; kt < KT; kt++) {
        int buf = kt & 1;
        if (kt + 1 < KT) { SET_SRC(kt + 1); FETCH(); }

#pragma unroll
        for (int k8 = 0; k8 < BK / 8; k8++) {
            unsigned af[4][4];
#pragma unroll
            for (int mt = 0; mt < 4; mt++) {
                int rb = wm0 + mt * 16 + (lane >> 2);
                af[mt][0] = As[buf][k8 * 8 + (lane & 3)][rb];
                af[mt][1] = As[buf][k8 * 8 + (lane & 3)][rb + 8];
                af[mt][2] = As[buf][k8 * 8 + 4 + (lane & 3)][rb];
                af[mt][3] = As[buf][k8 * 8 + 4 + (lane & 3)][rb + 8];
            }
            unsigned bf[4][2];
#pragma unroll
            for (int nt = 0; nt < 4; nt++) {
                int cb = wn0 + nt * 8 + (lane >> 2);
                bf[nt][0] = Bs[buf][k8 * 8 + (lane & 3)][cb];
                bf[nt][1] = Bs[buf][k8 * 8 + 4 + (lane & 3)][cb];
            }
#pragma unroll
            for (int mt = 0; mt < 4; mt++)
#pragma unroll
                for (int nt = 0; nt < 4; nt++)
                    mma_tf32(acc[mt][nt][0], acc[mt][nt][1], acc[mt][nt][2], acc[mt][nt][3],
                             af[mt][0], af[mt][1], af[mt][2], af[mt][3],
                             bf[nt][0], bf[nt][1]);
        }

        if (kt + 1 < KT) STORE((kt + 1) & 1);
        __syncthreads();
    }

    // ---- epilogue ----
#pragma unroll
    for (int mt = 0; mt < 4; mt++) {
        int row0 = m0 + wm0 + mt * 16 + (lane >> 2);
#pragma unroll
        for (int nt = 0; nt < 4; nt++) {
            int col0 = n0 + wn0 + nt * 8 + (lane & 3) * 2;
            float v0 = acc[mt][nt][0], v1 = acc[mt][nt][1];
            float v2 = acc[mt][nt][2], v3 = acc[mt][nt][3];
            if (mode == 0) {
                float gx = g_gam[col0], gy = g_gam[col0 + 1];
                *(float2*)&Cout[(size_t)row0 * DH + col0] = make_float2(v0 * gx, v1 * gy);
                *(float2*)&Cout[(size_t)(row0 + 8) * DH + col0] = make_float2(v2 * gx, v3 * gy);
            } else {
                float2 dv = *(const float2*)&Dvec[col0];
                float2 x0 = *(const float2*)&x[(size_t)row0 * DM + col0];
                float2 x1 = *(const float2*)&x[(size_t)(row0 + 8) * DM + col0];
                *(float2*)&Cout[(size_t)row0 * DM + col0] =
                    make_float2(v0 + x0.x * dv.x, v1 + x0.y * dv.y);
                *(float2*)&Cout[(size_t)(row0 + 8) * DM + col0] =
                    make_float2(v2 + x1.x * dv.x, v3 + x1.y * dv.y);
            }
        }
    }
}

// ---------------- scan pass A: per-chunk reduce ----------------
__global__ void chunk_reduce_kernel() {
    int c = blockIdx.x;
    int h = threadIdx.x;
    float lr = g_lam_re[h], li = g_lam_im[h];
    float sr = 0.f, si = 0.f;
    int any = 0;
    int base = c * LCH;
#pragma unroll 4
    for (int t = 0; t < LCH; t++) {
        int s = g_start[base + t];
        any |= s;
        float br = g_Bu_re[(size_t)(base + t) * DH + h];
        float bi = g_Bu_im[(size_t)(base + t) * DH + h];
        if (s) { sr = br; si = bi; }
        else {
            float nr = lr * sr - li * si + br;
            float ni = lr * si + li * sr + bi;
            sr = nr; si = ni;
        }
    }
    g_cb_re[c * DH + h] = sr;
    g_cb_im[c * DH + h] = si;
    if (h == 0) g_anystart[c] = any;
}

// ---------------- scan pass B: sequential scan over chunk carries ----------------
__global__ void chunk_scan_kernel(const float* __restrict__ state) {
    int h = threadIdx.x;
    float sr = state[h], si = 0.f;
    float Lr = g_lamL_re[h], Li = g_lamL_im[h];
    for (int c = 0; c < NCH; c++) {
        g_init_re[c * DH + h] = sr;
        g_init_im[c * DH + h] = si;
        float br = g_cb_re[c * DH + h];
        float bi = g_cb_im[c * DH + h];
        if (g_anystart[c]) { sr = br; si = bi; }
        else {
            float nr = Lr * sr - Li * si + br;
            float ni = Lr * si + Li * sr + bi;
            sr = nr; si = ni;
        }
    }
}

// ---------------- scan pass C: expand with correct chunk-initial states ----------------
__global__ void chunk_expand_kernel() {
    int c = blockIdx.x;
    int h = threadIdx.x;
    float lr = g_lam_re[h], li = g_lam_im[h];
    float sr = g_init_re[c * DH + h];
    float si = g_init_im[c * DH + h];
    int base = c * LCH;
#pragma unroll 4
    for (int t = 0; t < LCH; t++) {
        float br = g_Bu_re[(size_t)(base + t) * DH + h];
        float bi = g_Bu_im[(size_t)(base + t) * DH + h];
        if (g_start[base + t]) { sr = br; si = bi; }
        else {
            float nr = lr * sr - li * si + br;
            float ni = lr * si + li * sr + bi;
            sr = nr; si = ni;
        }
        g_xs_re[(size_t)(base + t) * DH + h] = sr;
        g_xs_im[(size_t)(base + t) * DH + h] = si;
    }
}

// ---------------- final state writer (planar layout: [re x 512][im x 512]) ----------------
__global__ void write_state_kernel(float* __restrict__ out, int mode) {
    int h = threadIdx.x;
    float re = g_xs_re[(size_t)(T_LEN - 1) * DH + h];
    float im = g_xs_im[(size_t)(T_LEN - 1) * DH + h];
    if (mode == 0) { out[h] = re; out[DH + h] = im; }
    else           { out[h] = re; }
}

// ---------------- launch ----------------
extern "C" void kernel_launch(void* const* d_in, const int* in_sizes, int n_in,
                              void* d_out, int out_size) {
    const float*        state     = (const float*)d_in[0];
    const float*        x         = (const float*)d_in[1];
    const unsigned int* start_raw = (const unsigned int*)d_in[2];
    const float*        theta_log = (const float*)d_in[3];
    const float*        nu_log    = (const float*)d_in[4];
    const float*        gamma_log = (const float*)d_in[5];
    const float*        B_re      = (const float*)d_in[6];
    const float*        B_im      = (const float*)d_in[7];
    const float*        C_re      = (const float*)d_in[8];
    const float*        C_im      = (const float*)d_in[9];
    const float*        Dvec      = (const float*)d_in[10];

    const long long full = (long long)T_LEN * DM;
    int state_elems = (int)((long long)out_size - full);
    int mode; int out_off;
    if (state_elems >= 2 * DH) { mode = 0; out_off = 2 * DH; }   // planar complex (verified)
    else                       { mode = 1; out_off = DH; }

    float* out = (float*)d_out;
    float* outputs = out + out_off;

    start_convert_kernel<<<1, 256>>>(start_raw);
    prep_kernel<<<1, DH>>>(theta_log, nu_log, gamma_log);

    // GEMM1: both Bu planes in one launch (blockIdx.z selects plane)
    dim3 g1(DH / 128, T_LEN / 128, 2);
    gemm_tc_kernel<<<g1, 256>>>(x, B_re, B_im, x, Dvec, nullptr, 0);

    chunk_reduce_kernel<<<NCH, DH>>>();
    chunk_scan_kernel<<<1, DH>>>(state);
    chunk_expand_kernel<<<NCH, DH>>>();

    // GEMM2: outputs
    dim3 g2(DM / 128, T_LEN / 128, 1);
    gemm_tc_kernel<<<g2, 256>>>(nullptr, C_re, C_im, x, Dvec, outputs, 2);

    write_state_kernel<<<1, DH>>>(out, mode);
}

// round 8
// speedup vs baseline: 2.9758x; 1.4267x over previous
#include <cuda_runtime.h>
#include <cstdint>

#define T_LEN 32768
#define DM 512
#define DH 512
#define LCH 32
#define NCH (T_LEN / LCH)   // 1024 chunks
#define NSUP 32             // super-chunks of 32 chunks
#define CPS (NCH / NSUP)    // 32 chunks per super

// ---------------- device scratch (no runtime allocations allowed) ----------------
__device__ float g_Bu_re[(size_t)T_LEN * DH];   // 64 MB
__device__ float g_Bu_im[(size_t)T_LEN * DH];   // 64 MB
__device__ float g_xs_re[(size_t)T_LEN * DH];   // 64 MB
__device__ float g_xs_im[(size_t)T_LEN * DH];   // 64 MB
__device__ float g_lam_re[DH], g_lam_im[DH], g_gam[DH];
__device__ float g_lamL_re[DH], g_lamL_im[DH];       // lambda^32
__device__ float g_lamS_re[DH], g_lamS_im[DH];       // lambda^1024
__device__ float g_cb_re[NCH * DH], g_cb_im[NCH * DH];
__device__ float g_init_re[NCH * DH], g_init_im[NCH * DH];
__device__ float g_sb_re[NSUP * DH], g_sb_im[NSUP * DH];
__device__ float g_sinit_re[NSUP * DH], g_sinit_im[NSUP * DH];
__device__ int   g_anystart[NCH];
__device__ int   g_sany[NSUP];
__device__ unsigned char g_start[T_LEN];

// ---------------- start-flag dtype detection + normalization ----------------
__global__ void start_convert_kernel(const unsigned int* __restrict__ raw) {
    __shared__ int s_isu8;
    int tid = threadIdx.x;
    if (tid == 0) s_isu8 = 0;
    __syncthreads();
    for (int i = tid; i < T_LEN / 4; i += blockDim.x)
        if (raw[i] > 1u) s_isu8 = 1;      // racy benign write
    __syncthreads();
    if (s_isu8) {
        const unsigned char* b = (const unsigned char*)raw;
        for (int t = tid; t < T_LEN; t += blockDim.x)
            g_start[t] = b[t] ? 1 : 0;
    } else {
        for (int t = tid; t < T_LEN; t += blockDim.x)
            g_start[t] = raw[t] ? 1 : 0;
    }
}

// ---------------- prep: lambda, gamma, lambda^32, lambda^1024 ----------------
__global__ void prep_kernel(const float* __restrict__ theta_log,
                            const float* __restrict__ nu_log,
                            const float* __restrict__ gamma_log) {
    int h = threadIdx.x;
    float nu = expf(nu_log[h]);
    float th = expf(theta_log[h]);
    float mag = expf(-nu);
    float lr = mag * cosf(th);
    float li = mag * sinf(th);
    g_lam_re[h] = lr;
    g_lam_im[h] = li;
    g_gam[h] = expf(gamma_log[h]);
    float ar = 1.f, ai = 0.f;
#pragma unroll
    for (int i = 0; i < LCH; i++) {
        float nr = ar * lr - ai * li;
        float ni = ar * li + ai * lr;
        ar = nr; ai = ni;
    }
    g_lamL_re[h] = ar;
    g_lamL_im[h] = ai;
    // lambda^1024 = (lambda^32)^32 sequentially
    float sr = 1.f, si = 0.f;
#pragma unroll
    for (int i = 0; i < CPS; i++) {
        float nr = sr * ar - si * ai;
        float ni = sr * ai + si * ar;
        sr = nr; si = ni;
    }
    g_lamS_re[h] = sr;
    g_lamS_im[h] = si;
}

// ---------------- tf32 helpers ----------------
__device__ __forceinline__ unsigned f2tf32(float x) {
    unsigned u;
    asm("cvt.rna.tf32.f32 %0, %1;" : "=r"(u) : "f"(x));
    return u;
}

__device__ __forceinline__ void mma_tf32(float& c0, float& c1, float& c2, float& c3,
                                         unsigned a0, unsigned a1, unsigned a2, unsigned a3,
                                         unsigned b0, unsigned b1) {
    asm volatile(
        "mma.sync.aligned.m16n8k8.row.col.f32.tf32.tf32.f32 "
        "{%0,%1,%2,%3}, {%4,%5,%6,%7}, {%8,%9}, {%0,%1,%2,%3};"
        : "+f"(c0), "+f"(c1), "+f"(c2), "+f"(c3)
        : "r"(a0), "r"(a1), "r"(a2), "r"(a3), "r"(b0), "r"(b1));
}

// ---------------- tensor-core GEMM (tf32) ----------------
// mode 0: Bu planes.  A = x (T,512);  B = (blockIdx.z ? B_im : B_re) [h,m].
//         Cout = (blockIdx.z ? g_Bu_im : g_Bu_re),  epilogue: * gam[col]. K=512.
// mode 2: outputs.    A = g_xs_re then g_xs_im;  B = C_re then -C_im. K=1024.
//         Cout = external outputs,  epilogue: + x*D.
// Tile: 128x128, BK=16 double-buffered, 8 warps (2m x 4n), warp tile 64x32.
// smem layout: row-major [m][k-permuted], stride 24 words; within a k8 group,
// k and k+4 are adjacent -> 64-bit fragment loads, conflict-free (12-unit
// 64-bit row stride covers all 32 banks exactly once across a warp).
#define BK 16
#define SMS 24

__global__ __launch_bounds__(256) void gemm_tc_kernel(
    const float* __restrict__ Agl,
    const float* __restrict__ B0,
    const float* __restrict__ B1,
    const float* __restrict__ x,
    const float* __restrict__ Dvec,
    float* __restrict__ Cout_ext,
    int mode)
{
    __shared__ unsigned As[2][128][SMS];
    __shared__ unsigned Bs[2][128][SMS];

    const int t    = threadIdx.x;
    const int lane = t & 31;
    const int wid  = t >> 5;
    const int wm0  = (wid >> 2) * 64;   // warp m offset in tile
    const int wn0  = (wid & 3) * 32;    // warp n offset in tile
    const int m0   = blockIdx.y * 128;
    const int n0   = blockIdx.x * 128;

    float* Cout;
    int KT;
    if (mode == 0) {
        Cout = blockIdx.z ? g_Bu_im : g_Bu_re;
        KT = DM / BK;               // 32
    } else {
        Cout = Cout_ext;
        KT = 2 * DH / BK;           // 64
    }

    const int lrow = t >> 2;        // 0..63, gmem load row within half-tile
    const int lk   = (t & 3) * 4;   // k quad base (0,4,8,12)
    const int sb   = ((lk >> 3) * 8) + ((lk >> 2) & 1);  // 0,1,8,9: permuted store base

    float acc[4][4][4];
#pragma unroll
    for (int a = 0; a < 4; a++)
#pragma unroll
        for (int b = 0; b < 4; b++)
#pragma unroll
            for (int c = 0; c < 4; c++) acc[a][b][c] = 0.f;

    const float* Ap; const float* Bp; float sgn; int kb;
#define SET_SRC(kt) do {                                              \
        int kg = (kt) * BK;                                           \
        if (mode == 0) { Ap = Agl; Bp = blockIdx.z ? B1 : B0; sgn = 1.f; kb = kg; } \
        else if (kg < DH) { Ap = g_xs_re; Bp = B0; sgn = 1.f;  kb = kg; }           \
        else              { Ap = g_xs_im; Bp = B1; sgn = -1.f; kb = kg - DH; }      \
    } while (0)

    float4 ra0, ra1, rb0, rb1;
#define FETCH() do {                                                                  \
        ra0 = *(const float4*)&Ap[(size_t)(m0 + lrow) * DM + kb + lk];                \
        ra1 = *(const float4*)&Ap[(size_t)(m0 + lrow + 64) * DM + kb + lk];           \
        rb0 = *(const float4*)&Bp[(size_t)(n0 + lrow) * DM + kb + lk];                \
        rb1 = *(const float4*)&Bp[(size_t)(n0 + lrow + 64) * DM + kb + lk];           \
    } while (0)

    // permuted store: k -> sb + 2*(k - lk)
#define STORE(buf) do {                                                \
        As[buf][lrow][sb + 0] = f2tf32(ra0.x);                         \
        As[buf][lrow][sb + 2] = f2tf32(ra0.y);                         \
        As[buf][lrow][sb + 4] = f2tf32(ra0.z);                         \
        As[buf][lrow][sb + 6] = f2tf32(ra0.w);                         \
        As[buf][lrow + 64][sb + 0] = f2tf32(ra1.x);                    \
        As[buf][lrow + 64][sb + 2] = f2tf32(ra1.y);                    \
        As[buf][lrow + 64][sb + 4] = f2tf32(ra1.z);                    \
        As[buf][lrow + 64][sb + 6] = f2tf32(ra1.w);                    \
        Bs[buf][lrow][sb + 0] = f2tf32(rb0.x * sgn);                   \
        Bs[buf][lrow][sb + 2] = f2tf32(rb0.y * sgn);                   \
        Bs[buf][lrow][sb + 4] = f2tf32(rb0.z * sgn);                   \
        Bs[buf][lrow][sb + 6] = f2tf32(rb0.w * sgn);                   \
        Bs[buf][lrow + 64][sb + 0] = f2tf32(rb1.x * sgn);              \
        Bs[buf][lrow + 64][sb + 2] = f2tf32(rb1.y * sgn);              \
        Bs[buf][lrow + 64][sb + 4] = f2tf32(rb1.z * sgn);              \
        Bs[buf][lrow + 64][sb + 6] = f2tf32(rb1.w * sgn);              \
    } while (0)

    SET_SRC(0); FETCH(); STORE(0);
    __syncthreads();

    const int q2 = (lane & 3) * 2;      // fragment k-pair offset
    const int fr = lane >> 2;           // fragment row/col within 8

    for (int kt = 0; kt < KT; kt++) {
        int buf = kt & 1;
        if (kt + 1 < KT) { SET_SRC(kt + 1); FETCH(); }

#pragma unroll
        for (int k8 = 0; k8 < BK / 8; k8++) {
            unsigned af[4][4];
#pragma unroll
            for (int mt = 0; mt < 4; mt++) {
                int rb = wm0 + mt * 16 + fr;
                uint2 lo = *(const uint2*)&As[buf][rb][k8 * 8 + q2];
                uint2 hi = *(const uint2*)&As[buf][rb + 8][k8 * 8 + q2];
                af[mt][0] = lo.x; af[mt][2] = lo.y;
                af[mt][1] = hi.x; af[mt][3] = hi.y;
            }
            unsigned bf[4][2];
#pragma unroll
            for (int nt = 0; nt < 4; nt++) {
                int cb = wn0 + nt * 8 + fr;
                uint2 bv = *(const uint2*)&Bs[buf][cb][k8 * 8 + q2];
                bf[nt][0] = bv.x; bf[nt][1] = bv.y;
            }
#pragma unroll
            for (int mt = 0; mt < 4; mt++)
#pragma unroll
                for (int nt = 0; nt < 4; nt++)
                    mma_tf32(acc[mt][nt][0], acc[mt][nt][1], acc[mt][nt][2], acc[mt][nt][3],
                             af[mt][0], af[mt][1], af[mt][2], af[mt][3],
                             bf[nt][0], bf[nt][1]);
        }

        if (kt + 1 < KT) STORE((kt + 1) & 1);
        __syncthreads();
    }

    // ---- epilogue ----
#pragma unroll
    for (int mt = 0; mt < 4; mt++) {
        int row0 = m0 + wm0 + mt * 16 + (lane >> 2);
#pragma unroll
        for (int nt = 0; nt < 4; nt++) {
            int col0 = n0 + wn0 + nt * 8 + (lane & 3) * 2;
            float v0 = acc[mt][nt][0], v1 = acc[mt][nt][1];
            float v2 = acc[mt][nt][2], v3 = acc[mt][nt][3];
            if (mode == 0) {
                float gx = g_gam[col0], gy = g_gam[col0 + 1];
                *(float2*)&Cout[(size_t)row0 * DH + col0] = make_float2(v0 * gx, v1 * gy);
                *(float2*)&Cout[(size_t)(row0 + 8) * DH + col0] = make_float2(v2 * gx, v3 * gy);
            } else {
                float2 dv = *(const float2*)&Dvec[col0];
                float2 x0 = *(const float2*)&x[(size_t)row0 * DM + col0];
                float2 x1 = *(const float2*)&x[(size_t)(row0 + 8) * DM + col0];
                *(float2*)&Cout[(size_t)row0 * DM + col0] =
                    make_float2(v0 + x0.x * dv.x, v1 + x0.y * dv.y);
                *(float2*)&Cout[(size_t)(row0 + 8) * DM + col0] =
                    make_float2(v2 + x1.x * dv.x, v3 + x1.y * dv.y);
            }
        }
    }
}

// ---------------- scan pass A: per-chunk reduce ----------------
__global__ void chunk_reduce_kernel() {
    int c = blockIdx.x;
    int h = threadIdx.x;
    float lr = g_lam_re[h], li = g_lam_im[h];
    float sr = 0.f, si = 0.f;
    int any = 0;
    int base = c * LCH;
#pragma unroll 4
    for (int t = 0; t < LCH; t++) {
        int s = g_start[base + t];
        any |= s;
        float br = g_Bu_re[(size_t)(base + t) * DH + h];
        float bi = g_Bu_im[(size_t)(base + t) * DH + h];
        if (s) { sr = br; si = bi; }
        else {
            float nr = lr * sr - li * si + br;
            float ni = lr * si + li * sr + bi;
            sr = nr; si = ni;
        }
    }
    g_cb_re[c * DH + h] = sr;
    g_cb_im[c * DH + h] = si;
    if (h == 0) g_anystart[c] = any;
}

// ---------------- scan B1: per-super reduce over chunk carries ----------------
__global__ void super_reduce_kernel() {
    int s = blockIdx.x;
    int h = threadIdx.x;
    float Lr = g_lamL_re[h], Li = g_lamL_im[h];
    float sr = 0.f, si = 0.f;
    int anyS = 0;
    int base = s * CPS;
#pragma unroll 4
    for (int j = 0; j < CPS; j++) {
        int c = base + j;
        int a = g_anystart[c];
        anyS |= a;
        float br = g_cb_re[c * DH + h];
        float bi = g_cb_im[c * DH + h];
        if (a) { sr = br; si = bi; }
        else {
            float nr = Lr * sr - Li * si + br;
            float ni = Lr * si + Li * sr + bi;
            sr = nr; si = ni;
        }
    }
    g_sb_re[s * DH + h] = sr;
    g_sb_im[s * DH + h] = si;
    if (h == 0) g_sany[s] = anyS;
}

// ---------------- scan B2: serial scan over 32 super carries ----------------
__global__ void super_scan_kernel(const float* __restrict__ state) {
    int h = threadIdx.x;
    float sr = state[h], si = 0.f;
    float Sr = g_lamS_re[h], Si = g_lamS_im[h];
#pragma unroll 4
    for (int s = 0; s < NSUP; s++) {
        g_sinit_re[s * DH + h] = sr;
        g_sinit_im[s * DH + h] = si;
        float br = g_sb_re[s * DH + h];
        float bi = g_sb_im[s * DH + h];
        if (g_sany[s]) { sr = br; si = bi; }
        else {
            float nr = Sr * sr - Si * si + br;
            float ni = Sr * si + Si * sr + bi;
            sr = nr; si = ni;
        }
    }
}

// ---------------- scan B3: rebuild per-chunk init states within each super ----------------
__global__ void super_expand_kernel() {
    int s = blockIdx.x;
    int h = threadIdx.x;
    float Lr = g_lamL_re[h], Li = g_lamL_im[h];
    float sr = g_sinit_re[s * DH + h];
    float si = g_sinit_im[s * DH + h];
    int base = s * CPS;
#pragma unroll 4
    for (int j = 0; j < CPS; j++) {
        int c = base + j;
        g_init_re[c * DH + h] = sr;
        g_init_im[c * DH + h] = si;
        float br = g_cb_re[c * DH + h];
        float bi = g_cb_im[c * DH + h];
        if (g_anystart[c]) { sr = br; si = bi; }
        else {
            float nr = Lr * sr - Li * si + br;
            float ni = Lr * si + Li * sr + bi;
            sr = nr; si = ni;
        }
    }
}

// ---------------- scan pass C: expand with chunk-initial states ----------------
__global__ void chunk_expand_kernel() {
    int c = blockIdx.x;
    int h = threadIdx.x;
    float lr = g_lam_re[h], li = g_lam_im[h];
    float sr = g_init_re[c * DH + h];
    float si = g_init_im[c * DH + h];
    int base = c * LCH;
#pragma unroll 4
    for (int t = 0; t < LCH; t++) {
        float br = g_Bu_re[(size_t)(base + t) * DH + h];
        float bi = g_Bu_im[(size_t)(base + t) * DH + h];
        if (g_start[base + t]) { sr = br; si = bi; }
        else {
            float nr = lr * sr - li * si + br;
            float ni = lr * si + li * sr + bi;
            sr = nr; si = ni;
        }
        g_xs_re[(size_t)(base + t) * DH + h] = sr;
        g_xs_im[(size_t)(base + t) * DH + h] = si;
    }
}

// ---------------- final state writer (planar layout: [re x 512][im x 512]) ----------------
__global__ void write_state_kernel(float* __restrict__ out, int mode) {
    int h = threadIdx.x;
    float re = g_xs_re[(size_t)(T_LEN - 1) * DH + h];
    float im = g_xs_im[(size_t)(T_LEN - 1) * DH + h];
    if (mode == 0) { out[h] = re; out[DH + h] = im; }
    else           { out[h] = re; }
}

// ---------------- launch ----------------
extern "C" void kernel_launch(void* const* d_in, const int* in_sizes, int n_in,
                              void* d_out, int out_size) {
    const float*        state     = (const float*)d_in[0];
    const float*        x         = (const float*)d_in[1];
    const unsigned int* start_raw = (const unsigned int*)d_in[2];
    const float*        theta_log = (const float*)d_in[3];
    const float*        nu_log    = (const float*)d_in[4];
    const float*        gamma_log = (const float*)d_in[5];
    const float*        B_re      = (const float*)d_in[6];
    const float*        B_im      = (const float*)d_in[7];
    const float*        C_re      = (const float*)d_in[8];
    const float*        C_im      = (const float*)d_in[9];
    const float*        Dvec      = (const float*)d_in[10];

    const long long full = (long long)T_LEN * DM;
    int state_elems = (int)((long long)out_size - full);
    int mode; int out_off;
    if (state_elems >= 2 * DH) { mode = 0; out_off = 2 * DH; }   // planar complex (verified)
    else                       { mode = 1; out_off = DH; }

    float* out = (float*)d_out;
    float* outputs = out + out_off;

    start_convert_kernel<<<1, 256>>>(start_raw);
    prep_kernel<<<1, DH>>>(theta_log, nu_log, gamma_log);

    // GEMM1: both Bu planes in one launch (blockIdx.z selects plane)
    dim3 g1(DH / 128, T_LEN / 128, 2);
    gemm_tc_kernel<<<g1, 256>>>(x, B_re, B_im, x, Dvec, nullptr, 0);

    chunk_reduce_kernel<<<NCH, DH>>>();
    super_reduce_kernel<<<NSUP, DH>>>();
    super_scan_kernel<<<1, DH>>>(state);
    super_expand_kernel<<<NSUP, DH>>>();
    chunk_expand_kernel<<<NCH, DH>>>();

    // GEMM2: outputs
    dim3 g2(DM / 128, T_LEN / 128, 1);
    gemm_tc_kernel<<<g2, 256>>>(nullptr, C_re, C_im, x, Dvec, outputs, 2);

    write_state_kernel<<<1, DH>>>(out, mode);
}

// round 11
// speedup vs baseline: 4.0484x; 1.3604x over previous
#include <cuda_runtime.h>
#include <cuda_fp16.h>
#include <cstdint>

#define T_LEN 32768
#define DM 512
#define DH 512
#define LCH 32
#define NCH (T_LEN / LCH)   // 1024 chunks
#define NSUP 32
#define CPS (NCH / NSUP)

// ---------------- device scratch ----------------
__device__ float g_Bu_re[(size_t)T_LEN * DH];
__device__ float g_Bu_im[(size_t)T_LEN * DH];
__device__ float g_xs_re[(size_t)T_LEN * DH];
__device__ float g_xs_im[(size_t)T_LEN * DH];
__device__ float g_lam_re[DH], g_lam_im[DH], g_gam[DH];
__device__ float g_lamL_re[DH], g_lamL_im[DH];
__device__ float g_lamS_re[DH], g_lamS_im[DH];
__device__ float g_cb_re[NCH * DH], g_cb_im[NCH * DH];
__device__ float g_init_re[NCH * DH], g_init_im[NCH * DH];
__device__ float g_sb_re[NSUP * DH], g_sb_im[NSUP * DH];
__device__ float g_sinit_re[NSUP * DH], g_sinit_im[NSUP * DH];
__device__ int   g_anystart[NCH];
__device__ int   g_sany[NSUP];
__device__ unsigned char g_start[T_LEN];

// ---------------- start-flag normalization ----------------
__global__ void start_convert_kernel(const unsigned int* __restrict__ raw) {
    __shared__ int s_isu8;
    int tid = threadIdx.x;
    if (tid == 0) s_isu8 = 0;
    __syncthreads();
    for (int i = tid; i < T_LEN / 4; i += blockDim.x)
        if (raw[i] > 1u) s_isu8 = 1;
    __syncthreads();
    if (s_isu8) {
        const unsigned char* b = (const unsigned char*)raw;
        for (int t = tid; t < T_LEN; t += blockDim.x) g_start[t] = b[t] ? 1 : 0;
    } else {
        for (int t = tid; t < T_LEN; t += blockDim.x) g_start[t] = raw[t] ? 1 : 0;
    }
}

// ---------------- prep ----------------
__global__ void prep_kernel(const float* __restrict__ theta_log,
                            const float* __restrict__ nu_log,
                            const float* __restrict__ gamma_log) {
    int h = threadIdx.x;
    float nu = expf(nu_log[h]);
    float th = expf(theta_log[h]);
    float mag = expf(-nu);
    float lr = mag * cosf(th);
    float li = mag * sinf(th);
    g_lam_re[h] = lr; g_lam_im[h] = li;
    g_gam[h] = expf(gamma_log[h]);
    float ar = 1.f, ai = 0.f;
#pragma unroll
    for (int i = 0; i < LCH; i++) {
        float nr = ar * lr - ai * li, ni = ar * li + ai * lr;
        ar = nr; ai = ni;
    }
    g_lamL_re[h] = ar; g_lamL_im[h] = ai;
    float sr = 1.f, si = 0.f;
#pragma unroll
    for (int i = 0; i < CPS; i++) {
        float nr = sr * ar - si * ai, ni = sr * ai + si * ar;
        sr = nr; si = ni;
    }
    g_lamS_re[h] = sr; g_lamS_im[h] = si;
}

// ---------------- fp16 helpers ----------------
__device__ __forceinline__ uint32_t pk_h2(float a, float b) {
    __half2 h = __floats2half2_rn(a, b);
    return *(uint32_t*)&h;
}

__device__ __forceinline__ void mma_f16(float& c0, float& c1, float& c2, float& c3,
                                        uint32_t a0, uint32_t a1, uint32_t a2, uint32_t a3,
                                        uint32_t b0, uint32_t b1) {
    asm volatile(
        "mma.sync.aligned.m16n8k16.row.col.f32.f16.f16.f32 "
        "{%0,%1,%2,%3}, {%4,%5,%6,%7}, {%8,%9}, {%0,%1,%2,%3};"
        : "+f"(c0), "+f"(c1), "+f"(c2), "+f"(c3)
        : "r"(a0), "r"(a1), "r"(a2), "r"(a3), "r"(b0), "r"(b1));
}

// ---------------- fp16 tensor-core GEMM ----------------
// mode 0: Bu planes. A = x (T,512); B = (blockIdx.z ? B_im : B_re) [h,m]. K=512, *gam.
// mode 2: outputs.   A = xs_re|xs_im; B = C_re|-C_im. K=1024, + x*D.
// Tile 128x128, BK=16 halves/row (32B), double-buffered, 8 warps (2m x 4n).
// smem word w holds half-pair; pair p stored at W = 2*((p&3)^s) + (p>>2),
// s = (row ^ row>>2) & 3  -> LDS.64 gives (2q,2q+1,2q+8,2q+9); stores & loads
// bank-conflict-free (per-phase bijections; W-sets disjoint across row groups).
#define BK 16

__global__ __launch_bounds__(256) void gemm_f16_kernel(
    const float* __restrict__ Agl,
    const float* __restrict__ B0,
    const float* __restrict__ B1,
    const float* __restrict__ x,
    const float* __restrict__ Dvec,
    float* __restrict__ Cout_ext,
    int mode)
{
    __shared__ uint32_t As[2][128 * 8];
    __shared__ uint32_t Bs[2][128 * 8];

    const int t    = threadIdx.x;
    const int lane = t & 31;
    const int wid  = t >> 5;
    const int wm0  = (wid >> 2) * 64;
    const int wn0  = (wid & 3) * 32;
    const int m0   = blockIdx.y * 128;
    const int n0   = blockIdx.x * 128;

    float* Cout;
    int KT;
    if (mode == 0) { Cout = blockIdx.z ? g_Bu_im : g_Bu_re; KT = DM / BK; }
    else           { Cout = Cout_ext;                       KT = 2 * DH / BK; }

    const int lrow = t >> 2;        // 0..63
    const int lk   = (t & 3) * 4;   // k float4 base
    const int p0   = lk >> 1;       // pair base (0,2,4,6)

    float acc[4][4][4];
#pragma unroll
    for (int a = 0; a < 4; a++)
#pragma unroll
        for (int b = 0; b < 4; b++)
#pragma unroll
            for (int c = 0; c < 4; c++) acc[a][b][c] = 0.f;

    const float* Ap; const float* Bp; float sgn; int kb;
#define SET_SRC(kt) do {                                              \
        int kg = (kt) * BK;                                           \
        if (mode == 0) { Ap = Agl; Bp = blockIdx.z ? B1 : B0; sgn = 1.f; kb = kg; } \
        else if (kg < DH) { Ap = g_xs_re; Bp = B0; sgn = 1.f;  kb = kg; }           \
        else              { Ap = g_xs_im; Bp = B1; sgn = -1.f; kb = kg - DH; }      \
    } while (0)

    float4 ra0, ra1, rb0, rb1;
#define FETCH() do {                                                                  \
        ra0 = *(const float4*)&Ap[(size_t)(m0 + lrow) * DM + kb + lk];                \
        ra1 = *(const float4*)&Ap[(size_t)(m0 + lrow + 64) * DM + kb + lk];           \
        rb0 = *(const float4*)&Bp[(size_t)(n0 + lrow) * DM + kb + lk];                \
        rb1 = *(const float4*)&Bp[(size_t)(n0 + lrow + 64) * DM + kb + lk];           \
    } while (0)

#define ST_ROW(arr, buf, row, v, sg) do {                              \
        int s_ = ((row) ^ ((row) >> 2)) & 3;                           \
        int W0_ = 2 * ((p0 & 3) ^ s_) + (p0 >> 2);                     \
        int W1_ = 2 * (((p0 + 1) & 3) ^ s_) + (p0 >> 2);               \
        arr[buf][(row) * 8 + W0_] = pk_h2((v).x * (sg), (v).y * (sg)); \
        arr[buf][(row) * 8 + W1_] = pk_h2((v).z * (sg), (v).w * (sg)); \
    } while (0)

#define STORE(buf) do {                          \
        ST_ROW(As, buf, lrow,      ra0, 1.f);    \
        ST_ROW(As, buf, lrow + 64, ra1, 1.f);    \
        ST_ROW(Bs, buf, lrow,      rb0, sgn);    \
        ST_ROW(Bs, buf, lrow + 64, rb1, sgn);    \
    } while (0)

    SET_SRC(0); FETCH(); STORE(0);
    __syncthreads();

    const int q  = lane & 3;
    const int fr = lane >> 2;

    for (int kt = 0; kt < KT; kt++) {
        int buf = kt & 1;
        if (kt + 1 < KT) { SET_SRC(kt + 1); FETCH(); }

        uint32_t af[4][4];
#pragma unroll
        for (int mt = 0; mt < 4; mt++) {
            int rb = wm0 + mt * 16 + fr;
            int s0 = (rb ^ (rb >> 2)) & 3;
            uint2 lo = *(const uint2*)&As[buf][rb * 8 + 2 * (q ^ s0)];
            int rb8 = rb + 8;
            int s8 = (rb8 ^ (rb8 >> 2)) & 3;
            uint2 hi = *(const uint2*)&As[buf][rb8 * 8 + 2 * (q ^ s8)];
            af[mt][0] = lo.x; af[mt][1] = hi.x;
            af[mt][2] = lo.y; af[mt][3] = hi.y;
        }
        uint32_t bf[4][2];
#pragma unroll
        for (int nt = 0; nt < 4; nt++) {
            int cb = wn0 + nt * 8 + fr;
            int sc = (cb ^ (cb >> 2)) & 3;
            uint2 bv = *(const uint2*)&Bs[buf][cb * 8 + 2 * (q ^ sc)];
            bf[nt][0] = bv.x; bf[nt][1] = bv.y;
        }
#pragma unroll
        for (int mt = 0; mt < 4; mt++)
#pragma unroll
            for (int nt = 0; nt < 4; nt++)
                mma_f16(acc[mt][nt][0], acc[mt][nt][1], acc[mt][nt][2], acc[mt][nt][3],
                        af[mt][0], af[mt][1], af[mt][2], af[mt][3],
                        bf[nt][0], bf[nt][1]);

        if (kt + 1 < KT) STORE((kt + 1) & 1);
        __syncthreads();
    }

    // ---- epilogue (same fragment D layout as m16n8k8) ----
#pragma unroll
    for (int mt = 0; mt < 4; mt++) {
        int row0 = m0 + wm0 + mt * 16 + (lane >> 2);
#pragma unroll
        for (int nt = 0; nt < 4; nt++) {
            int col0 = n0 + wn0 + nt * 8 + (lane & 3) * 2;
            float v0 = acc[mt][nt][0], v1 = acc[mt][nt][1];
            float v2 = acc[mt][nt][2], v3 = acc[mt][nt][3];
            if (mode == 0) {
                float gx = g_gam[col0], gy = g_gam[col0 + 1];
                *(float2*)&Cout[(size_t)row0 * DH + col0] = make_float2(v0 * gx, v1 * gy);
                *(float2*)&Cout[(size_t)(row0 + 8) * DH + col0] = make_float2(v2 * gx, v3 * gy);
            } else {
                float2 dv = *(const float2*)&Dvec[col0];
                float2 x0 = *(const float2*)&x[(size_t)row0 * DM + col0];
                float2 x1 = *(const float2*)&x[(size_t)(row0 + 8) * DM + col0];
                *(float2*)&Cout[(size_t)row0 * DM + col0] =
                    make_float2(v0 + x0.x * dv.x, v1 + x0.y * dv.y);
                *(float2*)&Cout[(size_t)(row0 + 8) * DM + col0] =
                    make_float2(v2 + x1.x * dv.x, v3 + x1.y * dv.y);
            }
        }
    }
}

// ---------------- scan passes ----------------
__global__ void chunk_reduce_kernel() {
    int c = blockIdx.x, h = threadIdx.x;
    float lr = g_lam_re[h], li = g_lam_im[h];
    float sr = 0.f, si = 0.f;
    int any = 0, base = c * LCH;
#pragma unroll 4
    for (int t = 0; t < LCH; t++) {
        int s = g_start[base + t];
        any |= s;
        float br = g_Bu_re[(size_t)(base + t) * DH + h];
        float bi = g_Bu_im[(size_t)(base + t) * DH + h];
        if (s) { sr = br; si = bi; }
        else {
            float nr = lr * sr - li * si + br, ni = lr * si + li * sr + bi;
            sr = nr; si = ni;
        }
    }
    g_cb_re[c * DH + h] = sr; g_cb_im[c * DH + h] = si;
    if (h == 0) g_anystart[c] = any;
}

__global__ void super_reduce_kernel() {
    int s = blockIdx.x, h = threadIdx.x;
    float Lr = g_lamL_re[h], Li = g_lamL_im[h];
    float sr = 0.f, si = 0.f;
    int anyS = 0, base = s * CPS;
#pragma unroll 4
    for (int j = 0; j < CPS; j++) {
        int c = base + j, a = g_anystart[c];
        anyS |= a;
        float br = g_cb_re[c * DH + h], bi = g_cb_im[c * DH + h];
        if (a) { sr = br; si = bi; }
        else {
            float nr = Lr * sr - Li * si + br, ni = Lr * si + Li * sr + bi;
            sr = nr; si = ni;
        }
    }
    g_sb_re[s * DH + h] = sr; g_sb_im[s * DH + h] = si;
    if (h == 0) g_sany[s] = anyS;
}

__global__ void super_scan_kernel(const float* __restrict__ state) {
    int h = threadIdx.x;
    float sr = state[h], si = 0.f;
    float Sr = g_lamS_re[h], Si = g_lamS_im[h];
#pragma unroll 4
    for (int s = 0; s < NSUP; s++) {
        g_sinit_re[s * DH + h] = sr; g_sinit_im[s * DH + h] = si;
        float br = g_sb_re[s * DH + h], bi = g_sb_im[s * DH + h];
        if (g_sany[s]) { sr = br; si = bi; }
        else {
            float nr = Sr * sr - Si * si + br, ni = Sr * si + Si * sr + bi;
            sr = nr; si = ni;
        }
    }
}

__global__ void super_expand_kernel() {
    int s = blockIdx.x, h = threadIdx.x;
    float Lr = g_lamL_re[h], Li = g_lamL_im[h];
    float sr = g_sinit_re[s * DH + h], si = g_sinit_im[s * DH + h];
    int base = s * CPS;
#pragma unroll 4
    for (int j = 0; j < CPS; j++) {
        int c = base + j;
        g_init_re[c * DH + h] = sr; g_init_im[c * DH + h] = si;
        float br = g_cb_re[c * DH + h], bi = g_cb_im[c * DH + h];
        if (g_anystart[c]) { sr = br; si = bi; }
        else {
            float nr = Lr * sr - Li * si + br, ni = Lr * si + Li * sr + bi;
            sr = nr; si = ni;
        }
    }
}

__global__ void chunk_expand_kernel() {
    int c = blockIdx.x, h = threadIdx.x;
    float lr = g_lam_re[h], li = g_lam_im[h];
    float sr = g_init_re[c * DH + h], si = g_init_im[c * DH + h];
    int base = c * LCH;
#pragma unroll 4
    for (int t = 0; t < LCH; t++) {
        float br = g_Bu_re[(size_t)(base + t) * DH + h];
        float bi = g_Bu_im[(size_t)(base + t) * DH + h];
        if (g_start[base + t]) { sr = br; si = bi; }
        else {
            float nr = lr * sr - li * si + br, ni = lr * si + li * sr + bi;
            sr = nr; si = ni;
        }
        g_xs_re[(size_t)(base + t) * DH + h] = sr;
        g_xs_im[(size_t)(base + t) * DH + h] = si;
    }
}

__global__ void write_state_kernel(float* __restrict__ out, int mode) {
    int h = threadIdx.x;
    float re = g_xs_re[(size_t)(T_LEN - 1) * DH + h];
    float im = g_xs_im[(size_t)(T_LEN - 1) * DH + h];
    if (mode == 0) { out[h] = re; out[DH + h] = im; }
    else           { out[h] = re; }
}

// ---------------- launch ----------------
extern "C" void kernel_launch(void* const* d_in, const int* in_sizes, int n_in,
                              void* d_out, int out_size) {
    const float*        state     = (const float*)d_in[0];
    const float*        x         = (const float*)d_in[1];
    const unsigned int* start_raw = (const unsigned int*)d_in[2];
    const float*        theta_log = (const float*)d_in[3];
    const float*        nu_log    = (const float*)d_in[4];
    const float*        gamma_log = (const float*)d_in[5];
    const float*        B_re      = (const float*)d_in[6];
    const float*        B_im      = (const float*)d_in[7];
    const float*        C_re      = (const float*)d_in[8];
    const float*        C_im      = (const float*)d_in[9];
    const float*        Dvec      = (const float*)d_in[10];

    const long long full = (long long)T_LEN * DM;
    int state_elems = (int)((long long)out_size - full);
    int mode; int out_off;
    if (state_elems >= 2 * DH) { mode = 0; out_off = 2 * DH; }
    else                       { mode = 1; out_off = DH; }

    float* out = (float*)d_out;
    float* outputs = out + out_off;

    start_convert_kernel<<<1, 256>>>(start_raw);
    prep_kernel<<<1, DH>>>(theta_log, nu_log, gamma_log);

    dim3 g1(DH / 128, T_LEN / 128, 2);
    gemm_f16_kernel<<<g1, 256>>>(x, B_re, B_im, x, Dvec, nullptr, 0);

    chunk_reduce_kernel<<<NCH, DH>>>();
    super_reduce_kernel<<<NSUP, DH>>>();
    super_scan_kernel<<<1, DH>>>(state);
    super_expand_kernel<<<NSUP, DH>>>();
    chunk_expand_kernel<<<NCH, DH>>>();

    dim3 g2(DM / 128, T_LEN / 128, 1);
    gemm_f16_kernel<<<g2, 256>>>(nullptr, C_re, C_im, x, Dvec, outputs, 2);

    write_state_kernel<<<1, DH>>>(out, mode);
}

// round 12
// speedup vs baseline: 6.3217x; 1.5615x over previous
#include <cuda_runtime.h>
#include <cuda_fp16.h>
#include <cstdint>

#define T_LEN 32768
#define DM 512
#define DH 512
#define LCH 32
#define NCH (T_LEN / LCH)
#define NSUP 32
#define CPS (NCH / NSUP)

#define STAGES 4
#define BKH 32                     // k per stage (halves)
#define STAGE_BYTES 16384          // A 8KB + B 8KB
#define SMEM_DYN (STAGES * STAGE_BYTES)   // 64 KB

// ---------------- device scratch ----------------
__device__ float  g_Bu_re[(size_t)T_LEN * DH];
__device__ float  g_Bu_im[(size_t)T_LEN * DH];
__device__ __half g_xh[(size_t)T_LEN * DM];
__device__ __half g_xsh_re[(size_t)T_LEN * DH];
__device__ __half g_xsh_im[(size_t)T_LEN * DH];
__device__ __half g_Bh[2][DH * DM];
__device__ __half g_Ch[2][DM * DH];     // Ch[1] = -C_im
__device__ float g_lam_re[DH], g_lam_im[DH], g_gam[DH];
__device__ float g_lamL_re[DH], g_lamL_im[DH];
__device__ float g_lamS_re[DH], g_lamS_im[DH];
__device__ float g_cb_re[NCH * DH], g_cb_im[NCH * DH];
__device__ float g_init_re[NCH * DH], g_init_im[NCH * DH];
__device__ float g_sb_re[NSUP * DH], g_sb_im[NSUP * DH];
__device__ float g_sinit_re[NSUP * DH], g_sinit_im[NSUP * DH];
__device__ float g_fin_re[DH], g_fin_im[DH];
__device__ int   g_anystart[NCH];
__device__ int   g_sany[NSUP];
__device__ unsigned char g_start[T_LEN];

// ---------------- start-flag normalization ----------------
__global__ void start_convert_kernel(const unsigned int* __restrict__ raw) {
    __shared__ int s_isu8;
    int tid = threadIdx.x;
    if (tid == 0) s_isu8 = 0;
    __syncthreads();
    for (int i = tid; i < T_LEN / 4; i += blockDim.x)
        if (raw[i] > 1u) s_isu8 = 1;
    __syncthreads();
    if (s_isu8) {
        const unsigned char* b = (const unsigned char*)raw;
        for (int t = tid; t < T_LEN; t += blockDim.x) g_start[t] = b[t] ? 1 : 0;
    } else {
        for (int t = tid; t < T_LEN; t += blockDim.x) g_start[t] = raw[t] ? 1 : 0;
    }
}

// ---------------- prep ----------------
__global__ void prep_kernel(const float* __restrict__ theta_log,
                            const float* __restrict__ nu_log,
                            const float* __restrict__ gamma_log) {
    int h = threadIdx.x;
    float nu = expf(nu_log[h]);
    float th = expf(theta_log[h]);
    float mag = expf(-nu);
    float lr = mag * cosf(th);
    float li = mag * sinf(th);
    g_lam_re[h] = lr; g_lam_im[h] = li;
    g_gam[h] = expf(gamma_log[h]);
    float ar = 1.f, ai = 0.f;
#pragma unroll
    for (int i = 0; i < LCH; i++) {
        float nr = ar * lr - ai * li, ni = ar * li + ai * lr;
        ar = nr; ai = ni;
    }
    g_lamL_re[h] = ar; g_lamL_im[h] = ai;
    float sr = 1.f, si = 0.f;
#pragma unroll
    for (int i = 0; i < CPS; i++) {
        float nr = sr * ar - si * ai, ni = sr * ai + si * ar;
        sr = nr; si = ni;
    }
    g_lamS_re[h] = sr; g_lamS_im[h] = si;
}

// ---------------- operand conversion ----------------
__global__ void convert_x_kernel(const float* __restrict__ x) {
    size_t i = (size_t)(blockIdx.x * blockDim.x + threadIdx.x) * 4;
    float4 v = *(const float4*)(x + i);
    *(__half2*)(g_xh + i)     = __floats2half2_rn(v.x, v.y);
    *(__half2*)(g_xh + i + 2) = __floats2half2_rn(v.z, v.w);
}

__global__ void convert_params_kernel(const float* __restrict__ B_re,
                                      const float* __restrict__ B_im,
                                      const float* __restrict__ C_re,
                                      const float* __restrict__ C_im) {
    int i = blockIdx.x * blockDim.x + threadIdx.x;
    g_Bh[0][i] = __float2half(B_re[i]);
    g_Bh[1][i] = __float2half(B_im[i]);
    g_Ch[0][i] = __float2half(C_re[i]);
    g_Ch[1][i] = __float2half(-C_im[i]);
}

// ---------------- asm helpers ----------------
__device__ __forceinline__ uint32_t smem_u32(const void* p) {
    uint32_t a;
    asm("{ .reg .u64 t; cvta.to.shared.u64 t, %1; cvt.u32.u64 %0, t; }" : "=r"(a) : "l"(p));
    return a;
}
__device__ __forceinline__ void cp16(uint32_t dst, const void* src) {
    asm volatile("cp.async.cg.shared.global [%0], [%1], 16;" :: "r"(dst), "l"(src));
}
#define CP_COMMIT() asm volatile("cp.async.commit_group;" ::: "memory")
#define CP_WAIT2()  asm volatile("cp.async.wait_group 2;" ::: "memory")
#define LDM_X4(r, a)                                                     \
    asm volatile("ldmatrix.sync.aligned.m8n8.x4.shared.b16 {%0,%1,%2,%3}, [%4];" \
        : "=r"((r)[0]), "=r"((r)[1]), "=r"((r)[2]), "=r"((r)[3]) : "r"(a))

__device__ __forceinline__ void mma_f16(float& c0, float& c1, float& c2, float& c3,
                                        uint32_t a0, uint32_t a1, uint32_t a2, uint32_t a3,
                                        uint32_t b0, uint32_t b1) {
    asm volatile(
        "mma.sync.aligned.m16n8k16.row.col.f32.f16.f16.f32 "
        "{%0,%1,%2,%3}, {%4,%5,%6,%7}, {%8,%9}, {%0,%1,%2,%3};"
        : "+f"(c0), "+f"(c1), "+f"(c2), "+f"(c3)
        : "r"(a0), "r"(a1), "r"(a2), "r"(a3), "r"(b0), "r"(b1));
}

// ---------------- pipelined fp16 GEMM ----------------
// mode 0: Bu planes. A = g_xh (T,512); B = g_Bh[z] (512,512). K=512. epi *gam.
// mode 2: outputs.   A = xsh_re|xsh_im; B = Ch0|Ch1(-C_im). K=1024. epi + x*D.
// Tile 128x128, 8 warps (2m x 4n), BK=32, 4-stage cp.async, ldmatrix fragments.
// smem: stage = A[64 lines x 128B] + B[same]; 16B chunk c of line L at c^(L&7).
__global__ __launch_bounds__(256) void gemm_f16p_kernel(
    const float* __restrict__ x, const float* __restrict__ Dvec,
    float* __restrict__ Cout_ext, int mode)
{
    extern __shared__ __align__(16) char dsm[];
    const uint32_t smb = smem_u32(dsm);

    const int t    = threadIdx.x;
    const int lane = t & 31;
    const int wid  = t >> 5;
    const int wm0  = (wid >> 2) * 64;
    const int wn0  = (wid & 3) * 32;
    const int m0   = blockIdx.y * 128;
    const int n0   = blockIdx.x * 128;

    float* Cout;
    int KT;
    if (mode == 0) { Cout = blockIdx.z ? g_Bu_im : g_Bu_re; KT = DM / BKH; }
    else           { Cout = Cout_ext;                       KT = 2 * DH / BKH; }

    float acc[4][4][4];
#pragma unroll
    for (int a = 0; a < 4; a++)
#pragma unroll
        for (int b = 0; b < 4; b++)
#pragma unroll
            for (int c = 0; c < 4; c++) acc[a][b][c] = 0.f;

    // per-thread cp.async chunk coords (2 chunks per matrix per stage)
    int cl[2], cs[2], cr[2], ck[2];
#pragma unroll
    for (int i = 0; i < 2; i++) {
        int g = t + i * 256;
        cl[i] = g >> 3;
        cs[i] = g & 7;
        cr[i] = (cl[i] << 1) + (cs[i] >> 2);
        ck[i] = (cs[i] & 3) * 8;
    }

#define ISSUE(s) do {                                                         \
        int kg = (s) * BKH;                                                   \
        const __half* Ap_; const __half* Bp_; int kb_;                        \
        if (mode == 0) { Ap_ = g_xh; Bp_ = g_Bh[blockIdx.z]; kb_ = kg; }      \
        else if (kg < DH) { Ap_ = g_xsh_re; Bp_ = g_Ch[0]; kb_ = kg; }        \
        else              { Ap_ = g_xsh_im; Bp_ = g_Ch[1]; kb_ = kg - DH; }   \
        uint32_t st_ = smb + ((s) % STAGES) * STAGE_BYTES;                    \
        _Pragma("unroll")                                                     \
        for (int i = 0; i < 2; i++) {                                         \
            uint32_t off = cl[i] * 128 + ((cs[i] ^ (cl[i] & 7)) << 4);        \
            cp16(st_ + off,        Ap_ + (size_t)(m0 + cr[i]) * DM + kb_ + ck[i]); \
            cp16(st_ + 8192 + off, Bp_ + (size_t)(n0 + cr[i]) * DM + kb_ + ck[i]); \
        }                                                                     \
    } while (0)

#pragma unroll
    for (int s = 0; s < STAGES - 1; s++) { ISSUE(s); CP_COMMIT(); }

    for (int kt = 0; kt < KT; kt++) {
        CP_WAIT2();
        __syncthreads();
        if (kt + STAGES - 1 < KT) ISSUE(kt + STAGES - 1);
        CP_COMMIT();

        uint32_t Ast = smb + (kt % STAGES) * STAGE_BYTES;
        uint32_t Bst = Ast + 8192;

#pragma unroll
        for (int j = 0; j < 2; j++) {
            uint32_t af[4][4];
#pragma unroll
            for (int mt = 0; mt < 4; mt++) {
                int r  = wm0 + mt * 16 + (lane & 7) + ((lane >> 3) & 1) * 8;
                int kc = 2 * j + (lane >> 4);
                int line = r >> 1, sub = ((r & 1) << 2) | kc;
                LDM_X4(af[mt], Ast + line * 128 + ((sub ^ (line & 7)) << 4));
            }
            uint32_t bq[2][4];
#pragma unroll
            for (int np = 0; np < 2; np++) {
                int n  = wn0 + np * 16 + (lane & 7) + ((lane >> 4) ? 8 : 0);
                int kc = 2 * j + ((lane >> 3) & 1);
                int line = n >> 1, sub = ((n & 1) << 2) | kc;
                LDM_X4(bq[np], Bst + line * 128 + ((sub ^ (line & 7)) << 4));
            }
#pragma unroll
            for (int mt = 0; mt < 4; mt++)
#pragma unroll
                for (int nt = 0; nt < 4; nt++)
                    mma_f16(acc[mt][nt][0], acc[mt][nt][1], acc[mt][nt][2], acc[mt][nt][3],
                            af[mt][0], af[mt][1], af[mt][2], af[mt][3],
                            bq[nt >> 1][(nt & 1) * 2], bq[nt >> 1][(nt & 1) * 2 + 1]);
        }
    }

    // ---- epilogue ----
#pragma unroll
    for (int mt = 0; mt < 4; mt++) {
        int row0 = m0 + wm0 + mt * 16 + (lane >> 2);
#pragma unroll
        for (int nt = 0; nt < 4; nt++) {
            int col0 = n0 + wn0 + nt * 8 + (lane & 3) * 2;
            float v0 = acc[mt][nt][0], v1 = acc[mt][nt][1];
            float v2 = acc[mt][nt][2], v3 = acc[mt][nt][3];
            if (mode == 0) {
                float gx = g_gam[col0], gy = g_gam[col0 + 1];
                *(float2*)&Cout[(size_t)row0 * DH + col0] = make_float2(v0 * gx, v1 * gy);
                *(float2*)&Cout[(size_t)(row0 + 8) * DH + col0] = make_float2(v2 * gx, v3 * gy);
            } else {
                float2 dv = *(const float2*)&Dvec[col0];
                float2 x0 = *(const float2*)&x[(size_t)row0 * DM + col0];
                float2 x1 = *(const float2*)&x[(size_t)(row0 + 8) * DM + col0];
                *(float2*)&Cout[(size_t)row0 * DM + col0] =
                    make_float2(v0 + x0.x * dv.x, v1 + x0.y * dv.y);
                *(float2*)&Cout[(size_t)(row0 + 8) * DM + col0] =
                    make_float2(v2 + x1.x * dv.x, v3 + x1.y * dv.y);
            }
        }
    }
}

// ---------------- scan passes ----------------
__global__ void chunk_reduce_kernel() {
    int c = blockIdx.x, h = threadIdx.x;
    float lr = g_lam_re[h], li = g_lam_im[h];
    float sr = 0.f, si = 0.f;
    int any = 0, base = c * LCH;
#pragma unroll 4
    for (int t = 0; t < LCH; t++) {
        int s = g_start[base + t];
        any |= s;
        float br = g_Bu_re[(size_t)(base + t) * DH + h];
        float bi = g_Bu_im[(size_t)(base + t) * DH + h];
        if (s) { sr = br; si = bi; }
        else {
            float nr = lr * sr - li * si + br, ni = lr * si + li * sr + bi;
            sr = nr; si = ni;
        }
    }
    g_cb_re[c * DH + h] = sr; g_cb_im[c * DH + h] = si;
    if (h == 0) g_anystart[c] = any;
}

__global__ void super_reduce_kernel() {
    int s = blockIdx.x, h = threadIdx.x;
    float Lr = g_lamL_re[h], Li = g_lamL_im[h];
    float sr = 0.f, si = 0.f;
    int anyS = 0, base = s * CPS;
#pragma unroll 4
    for (int j = 0; j < CPS; j++) {
        int c = base + j, a = g_anystart[c];
        anyS |= a;
        float br = g_cb_re[c * DH + h], bi = g_cb_im[c * DH + h];
        if (a) { sr = br; si = bi; }
        else {
            float nr = Lr * sr - Li * si + br, ni = Lr * si + Li * sr + bi;
            sr = nr; si = ni;
        }
    }
    g_sb_re[s * DH + h] = sr; g_sb_im[s * DH + h] = si;
    if (h == 0) g_sany[s] = anyS;
}

__global__ void super_scan_kernel(const float* __restrict__ state) {
    int h = threadIdx.x;
    float sr = state[h], si = 0.f;
    float Sr = g_lamS_re[h], Si = g_lamS_im[h];
#pragma unroll 4
    for (int s = 0; s < NSUP; s++) {
        g_sinit_re[s * DH + h] = sr; g_sinit_im[s * DH + h] = si;
        float br = g_sb_re[s * DH + h], bi = g_sb_im[s * DH + h];
        if (g_sany[s]) { sr = br; si = bi; }
        else {
            float nr = Sr * sr - Si * si + br, ni = Sr * si + Si * sr + bi;
            sr = nr; si = ni;
        }
    }
}

__global__ void super_expand_kernel() {
    int s = blockIdx.x, h = threadIdx.x;
    float Lr = g_lamL_re[h], Li = g_lamL_im[h];
    float sr = g_sinit_re[s * DH + h], si = g_sinit_im[s * DH + h];
    int base = s * CPS;
#pragma unroll 4
    for (int j = 0; j < CPS; j++) {
        int c = base + j;
        g_init_re[c * DH + h] = sr; g_init_im[c * DH + h] = si;
        float br = g_cb_re[c * DH + h], bi = g_cb_im[c * DH + h];
        if (g_anystart[c]) { sr = br; si = bi; }
        else {
            float nr = Lr * sr - Li * si + br, ni = Lr * si + Li * sr + bi;
            sr = nr; si = ni;
        }
    }
}

// expand: fp16 xs planes for GEMM2 + fp32 final-state capture
__global__ void chunk_expand_kernel() {
    int c = blockIdx.x, h = threadIdx.x;
    float lr = g_lam_re[h], li = g_lam_im[h];
    float sr = g_init_re[c * DH + h], si = g_init_im[c * DH + h];
    int base = c * LCH;
#pragma unroll 4
    for (int t = 0; t < LCH; t++) {
        float br = g_Bu_re[(size_t)(base + t) * DH + h];
        float bi = g_Bu_im[(size_t)(base + t) * DH + h];
        if (g_start[base + t]) { sr = br; si = bi; }
        else {
            float nr = lr * sr - li * si + br, ni = lr * si + li * sr + bi;
            sr = nr; si = ni;
        }
        g_xsh_re[(size_t)(base + t) * DH + h] = __float2half(sr);
        g_xsh_im[(size_t)(base + t) * DH + h] = __float2half(si);
    }
    if (c == NCH - 1) { g_fin_re[h] = sr; g_fin_im[h] = si; }
}

__global__ void write_state_kernel(float* __restrict__ out, int mode) {
    int h = threadIdx.x;
    if (mode == 0) { out[h] = g_fin_re[h]; out[DH + h] = g_fin_im[h]; }
    else           { out[h] = g_fin_re[h]; }
}

// ---------------- launch ----------------
extern "C" void kernel_launch(void* const* d_in, const int* in_sizes, int n_in,
                              void* d_out, int out_size) {
    const float*        state     = (const float*)d_in[0];
    const float*        x         = (const float*)d_in[1];
    const unsigned int* start_raw = (const unsigned int*)d_in[2];
    const float*        theta_log = (const float*)d_in[3];
    const float*        nu_log    = (const float*)d_in[4];
    const float*        gamma_log = (const float*)d_in[5];
    const float*        B_re      = (const float*)d_in[6];
    const float*        B_im      = (const float*)d_in[7];
    const float*        C_re      = (const float*)d_in[8];
    const float*        C_im      = (const float*)d_in[9];
    const float*        Dvec      = (const float*)d_in[10];

    const long long full = (long long)T_LEN * DM;
    int state_elems = (int)((long long)out_size - full);
    int mode; int out_off;
    if (state_elems >= 2 * DH) { mode = 0; out_off = 2 * DH; }
    else                       { mode = 1; out_off = DH; }

    float* out = (float*)d_out;
    float* outputs = out + out_off;

    static int smem_set = 0;
    if (!smem_set) {
        cudaFuncSetAttribute(gemm_f16p_kernel,
                             cudaFuncAttributeMaxDynamicSharedMemorySize, SMEM_DYN);
        smem_set = 1;
    }

    start_convert_kernel<<<1, 256>>>(start_raw);
    prep_kernel<<<1, DH>>>(theta_log, nu_log, gamma_log);
    convert_x_kernel<<<(T_LEN * DM / 4) / 256, 256>>>(x);
    convert_params_kernel<<<(DH * DM) / 256, 256>>>(B_re, B_im, C_re, C_im);

    dim3 g1(DH / 128, T_LEN / 128, 2);
    gemm_f16p_kernel<<<g1, 256, SMEM_DYN>>>(x, Dvec, nullptr, 0);

    chunk_reduce_kernel<<<NCH, DH>>>();
    super_reduce_kernel<<<NSUP, DH>>>();
    super_scan_kernel<<<1, DH>>>(state);
    super_expand_kernel<<<NSUP, DH>>>();
    chunk_expand_kernel<<<NCH, DH>>>();

    dim3 g2(DM / 128, T_LEN / 128, 1);
    gemm_f16p_kernel<<<g2, 256, SMEM_DYN>>>(x, Dvec, outputs, 2);

    write_state_kernel<<<1, DH>>>(out, mode);
}

// round 14
// speedup vs baseline: 6.5942x; 1.0431x over previous
#include <cuda_runtime.h>
#include <cuda_fp16.h>
#include <cstdint>

#define T_LEN 32768
#define DM 512
#define DH 512
#define LCH 32
#define NCH (T_LEN / LCH)
#define NSUP 32
#define CPS (NCH / NSUP)

#define STAGES 4
#define BKH 32
#define STAGE_BYTES 16384
#define SMEM_DYN (STAGES * STAGE_BYTES)   // 64 KB

// ---------------- device scratch ----------------
__device__ __half g_Buh_re[(size_t)T_LEN * DH];
__device__ __half g_Buh_im[(size_t)T_LEN * DH];
__device__ __half g_xh[(size_t)T_LEN * DM];
__device__ __half g_xsh_re[(size_t)T_LEN * DH];
__device__ __half g_xsh_im[(size_t)T_LEN * DH];
__device__ __half g_Bh[2][DH * DM];
__device__ __half g_Ch[2][DM * DH];     // Ch[1] = -C_im
__device__ float g_lam_re[DH], g_lam_im[DH], g_gam[DH];
__device__ float g_lamL_re[DH], g_lamL_im[DH];
__device__ float g_lamS_re[DH], g_lamS_im[DH];
__device__ float g_cb_re[NCH * DH], g_cb_im[NCH * DH];
__device__ float g_init_re[NCH * DH], g_init_im[NCH * DH];
__device__ float g_sb_re[NSUP * DH], g_sb_im[NSUP * DH];
__device__ float g_sinit_re[NSUP * DH], g_sinit_im[NSUP * DH];
__device__ float g_fin_re[DH], g_fin_im[DH];
__device__ int   g_anystart[NCH];
__device__ int   g_sany[NSUP];
__device__ unsigned char g_start[T_LEN];

// ---------------- start-flag normalization ----------------
__global__ void start_convert_kernel(const unsigned int* __restrict__ raw) {
    __shared__ int s_isu8;
    int tid = threadIdx.x;
    if (tid == 0) s_isu8 = 0;
    __syncthreads();
    for (int i = tid; i < T_LEN / 4; i += blockDim.x)
        if (raw[i] > 1u) s_isu8 = 1;
    __syncthreads();
    if (s_isu8) {
        const unsigned char* b = (const unsigned char*)raw;
        for (int t = tid; t < T_LEN; t += blockDim.x) g_start[t] = b[t] ? 1 : 0;
    } else {
        for (int t = tid; t < T_LEN; t += blockDim.x) g_start[t] = raw[t] ? 1 : 0;
    }
}

// ---------------- prep ----------------
__global__ void prep_kernel(const float* __restrict__ theta_log,
                            const float* __restrict__ nu_log,
                            const float* __restrict__ gamma_log) {
    int h = threadIdx.x;
    float nu = expf(nu_log[h]);
    float th = expf(theta_log[h]);
    float mag = expf(-nu);
    float lr = mag * cosf(th);
    float li = mag * sinf(th);
    g_lam_re[h] = lr; g_lam_im[h] = li;
    g_gam[h] = expf(gamma_log[h]);
    float ar = 1.f, ai = 0.f;
#pragma unroll
    for (int i = 0; i < LCH; i++) {
        float nr = ar * lr - ai * li, ni = ar * li + ai * lr;
        ar = nr; ai = ni;
    }
    g_lamL_re[h] = ar; g_lamL_im[h] = ai;
    float sr = 1.f, si = 0.f;
#pragma unroll
    for (int i = 0; i < CPS; i++) {
        float nr = sr * ar - si * ai, ni = sr * ai + si * ar;
        sr = nr; si = ni;
    }
    g_lamS_re[h] = sr; g_lamS_im[h] = si;
}

// ---------------- operand conversion ----------------
__global__ void convert_x_kernel(const float* __restrict__ x) {
    size_t i = (size_t)(blockIdx.x * blockDim.x + threadIdx.x) * 4;
    float4 v = *(const float4*)(x + i);
    *(__half2*)(g_xh + i)     = __floats2half2_rn(v.x, v.y);
    *(__half2*)(g_xh + i + 2) = __floats2half2_rn(v.z, v.w);
}

__global__ void convert_params_kernel(const float* __restrict__ B_re,
                                      const float* __restrict__ B_im,
                                      const float* __restrict__ C_re,
                                      const float* __restrict__ C_im) {
    int i = blockIdx.x * blockDim.x + threadIdx.x;
    g_Bh[0][i] = __float2half(B_re[i]);
    g_Bh[1][i] = __float2half(B_im[i]);
    g_Ch[0][i] = __float2half(C_re[i]);
    g_Ch[1][i] = __float2half(-C_im[i]);
}

// ---------------- asm helpers ----------------
__device__ __forceinline__ uint32_t smem_u32(const void* p) {
    uint32_t a;
    asm("{ .reg .u64 t; cvta.to.shared.u64 t, %1; cvt.u32.u64 %0, t; }" : "=r"(a) : "l"(p));
    return a;
}
__device__ __forceinline__ void cp16(uint32_t dst, const void* src) {
    asm volatile("cp.async.cg.shared.global [%0], [%1], 16;" :: "r"(dst), "l"(src));
}
#define CP_COMMIT() asm volatile("cp.async.commit_group;" ::: "memory")
#define CP_WAIT2()  asm volatile("cp.async.wait_group 2;" ::: "memory")
#define LDM_X4(r, a)                                                     \
    asm volatile("ldmatrix.sync.aligned.m8n8.x4.shared.b16 {%0,%1,%2,%3}, [%4];" \
        : "=r"((r)[0]), "=r"((r)[1]), "=r"((r)[2]), "=r"((r)[3]) : "r"(a))

__device__ __forceinline__ void mma_f16(float& c0, float& c1, float& c2, float& c3,
                                        uint32_t a0, uint32_t a1, uint32_t a2, uint32_t a3,
                                        uint32_t b0, uint32_t b1) {
    asm volatile(
        "mma.sync.aligned.m16n8k16.row.col.f32.f16.f16.f32 "
        "{%0,%1,%2,%3}, {%4,%5,%6,%7}, {%8,%9}, {%0,%1,%2,%3};"
        : "+f"(c0), "+f"(c1), "+f"(c2), "+f"(c3)
        : "r"(a0), "r"(a1), "r"(a2), "r"(a3), "r"(b0), "r"(b1));
}

// ---------------- pipelined fp16 GEMM ----------------
// mode 0: Bu planes. A = g_xh; B = g_Bh[z]. K=512. epi *gam -> half Bu planes.
// mode 2: outputs.   A = xsh_re|xsh_im; B = Ch0|Ch1. K=1024. epi + x*D (fp32 out).
// Tile 128x128, 8 warps (2m x 4n), BK=32, 4-stage cp.async, ldmatrix, 2 CTAs/SM.
__global__ __launch_bounds__(256, 2) void gemm_f16p_kernel(
    const float* __restrict__ x, const float* __restrict__ Dvec,
    float* __restrict__ Cout_ext, int mode)
{
    extern __shared__ __align__(16) char dsm[];
    const uint32_t smb = smem_u32(dsm);

    const int t    = threadIdx.x;
    const int lane = t & 31;
    const int wid  = t >> 5;
    const int wm0  = (wid >> 2) * 64;
    const int wn0  = (wid & 3) * 32;
    const int m0   = blockIdx.y * 128;
    const int n0   = blockIdx.x * 128;

    int KT = (mode == 0) ? DM / BKH : 2 * DH / BKH;

    float acc[4][4][4];
#pragma unroll
    for (int a = 0; a < 4; a++)
#pragma unroll
        for (int b = 0; b < 4; b++)
#pragma unroll
            for (int c = 0; c < 4; c++) acc[a][b][c] = 0.f;

    int cl[2], cs[2], cr[2], ck[2];
#pragma unroll
    for (int i = 0; i < 2; i++) {
        int g = t + i * 256;
        cl[i] = g >> 3;
        cs[i] = g & 7;
        cr[i] = (cl[i] << 1) + (cs[i] >> 2);
        ck[i] = (cs[i] & 3) * 8;
    }

#define ISSUE(s) do {                                                         \
        int kg = (s) * BKH;                                                   \
        const __half* Ap_; const __half* Bp_; int kb_;                        \
        if (mode == 0) { Ap_ = g_xh; Bp_ = g_Bh[blockIdx.z]; kb_ = kg; }      \
        else if (kg < DH) { Ap_ = g_xsh_re; Bp_ = g_Ch[0]; kb_ = kg; }        \
        else              { Ap_ = g_xsh_im; Bp_ = g_Ch[1]; kb_ = kg - DH; }   \
        uint32_t st_ = smb + ((s) % STAGES) * STAGE_BYTES;                    \
        _Pragma("unroll")                                                     \
        for (int i = 0; i < 2; i++) {                                         \
            uint32_t off = cl[i] * 128 + ((cs[i] ^ (cl[i] & 7)) << 4);        \
            cp16(st_ + off,        Ap_ + (size_t)(m0 + cr[i]) * DM + kb_ + ck[i]); \
            cp16(st_ + 8192 + off, Bp_ + (size_t)(n0 + cr[i]) * DM + kb_ + ck[i]); \
        }                                                                     \
    } while (0)

#pragma unroll
    for (int s = 0; s < STAGES - 1; s++) { ISSUE(s); CP_COMMIT(); }

    for (int kt = 0; kt < KT; kt++) {
        CP_WAIT2();
        __syncthreads();
        if (kt + STAGES - 1 < KT) ISSUE(kt + STAGES - 1);
        CP_COMMIT();

        uint32_t Ast = smb + (kt % STAGES) * STAGE_BYTES;
        uint32_t Bst = Ast + 8192;

#pragma unroll
        for (int j = 0; j < 2; j++) {
            uint32_t af[4][4];
#pragma unroll
            for (int mt = 0; mt < 4; mt++) {
                int r  = wm0 + mt * 16 + (lane & 7) + ((lane >> 3) & 1) * 8;
                int kc = 2 * j + (lane >> 4);
                int line = r >> 1, sub = ((r & 1) << 2) | kc;
                LDM_X4(af[mt], Ast + line * 128 + ((sub ^ (line & 7)) << 4));
            }
            uint32_t bq[2][4];
#pragma unroll
            for (int np = 0; np < 2; np++) {
                int n  = wn0 + np * 16 + (lane & 7) + ((lane >> 4) ? 8 : 0);
                int kc = 2 * j + ((lane >> 3) & 1);
                int line = n >> 1, sub = ((n & 1) << 2) | kc;
                LDM_X4(bq[np], Bst + line * 128 + ((sub ^ (line & 7)) << 4));
            }
#pragma unroll
            for (int mt = 0; mt < 4; mt++)
#pragma unroll
                for (int nt = 0; nt < 4; nt++)
                    mma_f16(acc[mt][nt][0], acc[mt][nt][1], acc[mt][nt][2], acc[mt][nt][3],
                            af[mt][0], af[mt][1], af[mt][2], af[mt][3],
                            bq[nt >> 1][(nt & 1) * 2], bq[nt >> 1][(nt & 1) * 2 + 1]);
        }
    }

    // ---- epilogue ----
#pragma unroll
    for (int mt = 0; mt < 4; mt++) {
        int row0 = m0 + wm0 + mt * 16 + (lane >> 2);
#pragma unroll
        for (int nt = 0; nt < 4; nt++) {
            int col0 = n0 + wn0 + nt * 8 + (lane & 3) * 2;
            float v0 = acc[mt][nt][0], v1 = acc[mt][nt][1];
            float v2 = acc[mt][nt][2], v3 = acc[mt][nt][3];
            if (mode == 0) {
                __half* base = blockIdx.z ? g_Buh_im : g_Buh_re;
                float gx = g_gam[col0], gy = g_gam[col0 + 1];
                *(__half2*)&base[(size_t)row0 * DH + col0] =
                    __floats2half2_rn(v0 * gx, v1 * gy);
                *(__half2*)&base[(size_t)(row0 + 8) * DH + col0] =
                    __floats2half2_rn(v2 * gx, v3 * gy);
            } else {
                float2 dv = *(const float2*)&Dvec[col0];
                float2 x0 = *(const float2*)&x[(size_t)row0 * DM + col0];
                float2 x1 = *(const float2*)&x[(size_t)(row0 + 8) * DM + col0];
                *(float2*)&Cout_ext[(size_t)row0 * DM + col0] =
                    make_float2(v0 + x0.x * dv.x, v1 + x0.y * dv.y);
                *(float2*)&Cout_ext[(size_t)(row0 + 8) * DM + col0] =
                    make_float2(v2 + x1.x * dv.x, v3 + x1.y * dv.y);
            }
        }
    }
}

// ---------------- scan passes ----------------
__global__ void chunk_reduce_kernel() {
    int c = blockIdx.x, h = threadIdx.x;
    float lr = g_lam_re[h], li = g_lam_im[h];
    float sr = 0.f, si = 0.f;
    int any = 0, base = c * LCH;
#pragma unroll 4
    for (int t = 0; t < LCH; t++) {
        int s = g_start[base + t];
        any |= s;
        float br = __half2float(g_Buh_re[(size_t)(base + t) * DH + h]);
        float bi = __half2float(g_Buh_im[(size_t)(base + t) * DH + h]);
        if (s) { sr = br; si = bi; }
        else {
            float nr = lr * sr - li * si + br, ni = lr * si + li * sr + bi;
            sr = nr; si = ni;
        }
    }
    g_cb_re[c * DH + h] = sr; g_cb_im[c * DH + h] = si;
    if (h == 0) g_anystart[c] = any;
}

__global__ void super_reduce_kernel() {
    int s = blockIdx.x, h = threadIdx.x;
    float Lr = g_lamL_re[h], Li = g_lamL_im[h];
    float sr = 0.f, si = 0.f;
    int anyS = 0, base = s * CPS;
#pragma unroll 4
    for (int j = 0; j < CPS; j++) {
        int c = base + j, a = g_anystart[c];
        anyS |= a;
        float br = g_cb_re[c * DH + h], bi = g_cb_im[c * DH + h];
        if (a) { sr = br; si = bi; }
        else {
            float nr = Lr * sr - Li * si + br, ni = Lr * si + Li * sr + bi;
            sr = nr; si = ni;
        }
    }
    g_sb_re[s * DH + h] = sr; g_sb_im[s * DH + h] = si;
    if (h == 0) g_sany[s] = anyS;
}

__global__ void super_scan_kernel(const float* __restrict__ state) {
    int h = threadIdx.x;
    float sr = state[h], si = 0.f;
    float Sr = g_lamS_re[h], Si = g_lamS_im[h];
#pragma unroll 4
    for (int s = 0; s < NSUP; s++) {
        g_sinit_re[s * DH + h] = sr; g_sinit_im[s * DH + h] = si;
        float br = g_sb_re[s * DH + h], bi = g_sb_im[s * DH + h];
        if (g_sany[s]) { sr = br; si = bi; }
        else {
            float nr = Sr * sr - Si * si + br, ni = Sr * si + Si * sr + bi;
            sr = nr; si = ni;
        }
    }
}

__global__ void super_expand_kernel() {
    int s = blockIdx.x, h = threadIdx.x;
    float Lr = g_lamL_re[h], Li = g_lamL_im[h];
    float sr = g_sinit_re[s * DH + h], si = g_sinit_im[s * DH + h];
    int base = s * CPS;
#pragma unroll 4
    for (int j = 0; j < CPS; j++) {
        int c = base + j;
        g_init_re[c * DH + h] = sr; g_init_im[c * DH + h] = si;
        float br = g_cb_re[c * DH + h], bi = g_cb_im[c * DH + h];
        if (g_anystart[c]) { sr = br; si = bi; }
        else {
            float nr = Lr * sr - Li * si + br, ni = Lr * si + Li * sr + bi;
            sr = nr; si = ni;
        }
    }
}

// expand: fp16 xs planes for GEMM2 + fp32 final-state capture
__global__ void chunk_expand_kernel() {
    int c = blockIdx.x, h = threadIdx.x;
    float lr = g_lam_re[h], li = g_lam_im[h];
    float sr = g_init_re[c * DH + h], si = g_init_im[c * DH + h];
    int base = c * LCH;
#pragma unroll 4
    for (int t = 0; t < LCH; t++) {
        float br = __half2float(g_Buh_re[(size_t)(base + t) * DH + h]);
        float bi = __half2float(g_Buh_im[(size_t)(base + t) * DH + h]);
        if (g_start[base + t]) { sr = br; si = bi; }
        else {
            float nr = lr * sr - li * si + br, ni = lr * si + li * sr + bi;
            sr = nr; si = ni;
        }
        g_xsh_re[(size_t)(base + t) * DH + h] = __float2half(sr);
        g_xsh_im[(size_t)(base + t) * DH + h] = __float2half(si);
    }
    if (c == NCH - 1) { g_fin_re[h] = sr; g_fin_im[h] = si; }
}

__global__ void write_state_kernel(float* __restrict__ out, int mode) {
    int h = threadIdx.x;
    if (mode == 0) { out[h] = g_fin_re[h]; out[DH + h] = g_fin_im[h]; }
    else           { out[h] = g_fin_re[h]; }
}

// ---------------- launch ----------------
extern "C" void kernel_launch(void* const* d_in, const int* in_sizes, int n_in,
                              void* d_out, int out_size) {
    const float*        state     = (const float*)d_in[0];
    const float*        x         = (const float*)d_in[1];
    const unsigned int* start_raw = (const unsigned int*)d_in[2];
    const float*        theta_log = (const float*)d_in[3];
    const float*        nu_log    = (const float*)d_in[4];
    const float*        gamma_log = (const float*)d_in[5];
    const float*        B_re      = (const float*)d_in[6];
    const float*        B_im      = (const float*)d_in[7];
    const float*        C_re      = (const float*)d_in[8];
    const float*        C_im      = (const float*)d_in[9];
    const float*        Dvec      = (const float*)d_in[10];

    const long long full = (long long)T_LEN * DM;
    int state_elems = (int)((long long)out_size - full);
    int mode; int out_off;
    if (state_elems >= 2 * DH) { mode = 0; out_off = 2 * DH; }
    else                       { mode = 1; out_off = DH; }

    float* out = (float*)d_out;
    float* outputs = out + out_off;

    static int smem_set = 0;
    if (!smem_set) {
        cudaFuncSetAttribute(gemm_f16p_kernel,
                             cudaFuncAttributeMaxDynamicSharedMemorySize, SMEM_DYN);
        smem_set = 1;
    }

    start_convert_kernel<<<1, 256>>>(start_raw);
    prep_kernel<<<1, DH>>>(theta_log, nu_log, gamma_log);
    convert_x_kernel<<<(T_LEN * DM / 4) / 256, 256>>>(x);
    convert_params_kernel<<<(DH * DM) / 256, 256>>>(B_re, B_im, C_re, C_im);

    dim3 g1(DH / 128, T_LEN / 128, 2);
    gemm_f16p_kernel<<<g1, 256, SMEM_DYN>>>(x, Dvec, nullptr, 0);

    chunk_reduce_kernel<<<NCH, DH>>>();
    super_reduce_kernel<<<NSUP, DH>>>();
    super_scan_kernel<<<1, DH>>>(state);
    super_expand_kernel<<<NSUP, DH>>>();
    chunk_expand_kernel<<<NCH, DH>>>();

    dim3 g2(DM / 128, T_LEN / 128, 1);
    gemm_f16p_kernel<<<g2, 256, SMEM_DYN>>>(x, Dvec, outputs, 2);

    write_state_kernel<<<1, DH>>>(out, mode);
}